// round 9
// baseline (speedup 1.0000x reference)
#include <cuda_runtime.h>
#include <cuda_bf16.h>
#include <stdint.h>
#include <math.h>

// ---------------------------------------------------------------------------
// QuantumGeometricAttention forward.  Complex HMMA GEMMs with Gauss 3-product
// trick (9 bf16 hi/lo passes instead of 12), cp.async double buffering (BK=16,
// 48B row pitch for 16B alignment), Hermitian scores (fp32 + SMEM transpose).
// ---------------------------------------------------------------------------

#define BATCH 2
#define SEQ   2048
#define HID   1024
#define MAN   1024
#define ROWS  (BATCH * SEQ)
#define NLAYERS 3

typedef __nv_bfloat16 bf16;

// ---------------- fp32 scratch ----------------------------------------------
__device__ float g_sr [(size_t)BATCH * SEQ * SEQ];
__device__ float g_si [(size_t)BATCH * SEQ * SEQ];

// ---------------- bf16 hi/lo planes (hi at 0, lo at +plane) ------------------
__device__ bf16 c_x    [2 * (size_t)ROWS * HID];
__device__ bf16 c_wp   [2 * (size_t)MAN * HID];
__device__ bf16 c_wpinv[2 * (size_t)HID * MAN];
__device__ bf16 c_wr   [2 * (size_t)MAN * MAN];
__device__ bf16 c_wi   [2 * (size_t)MAN * MAN];
__device__ bf16 c_wsum [2 * (size_t)MAN * MAN];
__device__ bf16 c_met  [2 * (size_t)MAN * MAN];
__device__ bf16 c_m0   [2 * (size_t)MAN * MAN];
__device__ bf16 c_m1   [2 * (size_t)MAN * MAN];
__device__ bf16 c_m2   [2 * (size_t)MAN * MAN];
__device__ bf16 c_cpost[2 * (size_t)MAN * HID];
__device__ bf16 c_q0r  [2 * (size_t)ROWS * MAN];
__device__ bf16 c_q0i  [2 * (size_t)ROWS * MAN];
__device__ bf16 c_q0s  [2 * (size_t)ROWS * MAN];
__device__ bf16 c_q1r  [2 * (size_t)ROWS * MAN];
__device__ bf16 c_q1i  [2 * (size_t)ROWS * MAN];
__device__ bf16 c_q1s  [2 * (size_t)ROWS * MAN];
__device__ bf16 c_ar   [2 * (size_t)ROWS * MAN];
__device__ bf16 c_ai   [2 * (size_t)ROWS * MAN];
__device__ bf16 c_as   [2 * (size_t)ROWS * MAN];
__device__ bf16 c_ad   [2 * (size_t)ROWS * MAN];
__device__ bf16 c_sr   [2 * (size_t)BATCH * SEQ * SEQ];
__device__ bf16 c_si   [2 * (size_t)BATCH * SEQ * SEQ];
__device__ bf16 c_ss   [2 * (size_t)BATCH * SEQ * SEQ];

// ---------------------------- helpers ---------------------------------------
__device__ __forceinline__ uint32_t smem_u32(const void* p) {
    uint32_t a;
    asm("{ .reg .u64 t; cvta.to.shared.u64 t, %1; cvt.u32.u64 %0, t; }" : "=r"(a) : "l"(p));
    return a;
}
__device__ __forceinline__ void cp16(uint32_t dst, const void* src) {
    asm volatile("{ .reg .u64 g; cvta.to.global.u64 g, %1; cp.async.cg.shared.global [%0], [g], 16; }"
                 :: "r"(dst), "l"(src) : "memory");
}
#define CP_COMMIT() asm volatile("cp.async.commit_group;" ::: "memory")
#define CP_WAIT(n)  asm volatile("cp.async.wait_group %0;" :: "n"(n) : "memory")

#define MMA(d, a, b0, b1) \
    asm volatile("mma.sync.aligned.m16n8k16.row.col.f32.bf16.bf16.f32 " \
        "{%0,%1,%2,%3}, {%4,%5,%6,%7}, {%8,%9}, {%0,%1,%2,%3};" \
        : "+f"((d)[0]), "+f"((d)[1]), "+f"((d)[2]), "+f"((d)[3]) \
        : "r"((a)[0]), "r"((a)[1]), "r"((a)[2]), "r"((a)[3]), "r"(b0), "r"(b1))

__device__ __forceinline__ uint32_t pack_hi2(float a, float b, float& ra, float& rb) {
    bf16 h0 = __float2bfloat16(a), h1 = __float2bfloat16(b);
    ra = a - __bfloat162float(h0); rb = b - __bfloat162float(h1);
    return (uint32_t)__bfloat16_as_ushort(h0) | ((uint32_t)__bfloat16_as_ushort(h1) << 16);
}
__device__ __forceinline__ uint32_t pack2(float a, float b) {
    return (uint32_t)__bfloat16_as_ushort(__float2bfloat16(a)) |
           ((uint32_t)__bfloat16_as_ushort(__float2bfloat16(b)) << 16);
}

// ---------------------------------------------------------------------------
// fp32 -> bf16 hi/lo convert (and two-input-sum variant)
// ---------------------------------------------------------------------------
__global__ __launch_bounds__(256)
void convert_hilo_kernel(const float* __restrict__ src, bf16* __restrict__ dst,
                         long long n4, long long plane)
{
    long long i = (long long)blockIdx.x * blockDim.x + threadIdx.x;
    if (i >= n4) return;
    float4 v = ((const float4*)src)[i];
    float r0, r1, r2, r3;
    uint2 hp, lp;
    hp.x = pack_hi2(v.x, v.y, r0, r1);
    hp.y = pack_hi2(v.z, v.w, r2, r3);
    lp.x = pack2(r0, r1);
    lp.y = pack2(r2, r3);
    ((uint2*)dst)[i] = hp;
    ((uint2*)(dst + plane))[i] = lp;
}

__global__ __launch_bounds__(256)
void convert_hilo_sum_kernel(const float* __restrict__ a, const float* __restrict__ b,
                             bf16* __restrict__ dst, long long n4, long long plane)
{
    long long i = (long long)blockIdx.x * blockDim.x + threadIdx.x;
    if (i >= n4) return;
    float4 va = ((const float4*)a)[i];
    float4 vb = ((const float4*)b)[i];
    float4 v = make_float4(va.x + vb.x, va.y + vb.y, va.z + vb.z, va.w + vb.w);
    float r0, r1, r2, r3;
    uint2 hp, lp;
    hp.x = pack_hi2(v.x, v.y, r0, r1);
    hp.y = pack_hi2(v.z, v.w, r2, r3);
    lp.x = pack2(r0, r1);
    lp.y = pack2(r2, r3);
    ((uint2*)dst)[i] = hp;
    ((uint2*)(dst + plane))[i] = lp;
}

// ---------------------------------------------------------------------------
// Real HMMA GEMM (BK=32), bf16 hi/lo 3-pass; writes fp32 or bf16 planes.
// ---------------------------------------------------------------------------
template<bool TRANSB, bool WB16>
__global__ __launch_bounds__(256, 2)
void hgemm_kernel(const bf16* __restrict__ A, const bf16* __restrict__ B,
                  float* __restrict__ Cf, bf16* __restrict__ Cb, long long planeC,
                  const float* __restrict__ bias,
                  int M, int N, int K,
                  long long planeA, long long planeB,
                  float alpha)
{
    __shared__ __align__(16) bf16 sAm[2][128][40];
    __shared__ __align__(16) bf16 sBm[2][5120];

    const int bm = blockIdx.y * 128;
    const int bn = blockIdx.x * 128;
    const int t = threadIdx.x, wid = t >> 5, lane = t & 31;
    const int wm = (wid >> 2) * 64, wn = (wid & 3) * 32;

    float acc[4][4][4];
#pragma unroll
    for (int a = 0; a < 4; a++)
#pragma unroll
        for (int b = 0; b < 4; b++)
#pragma unroll
            for (int c = 0; c < 4; c++) acc[a][b][c] = 0.f;

    for (int k0 = 0; k0 < K; k0 += 32) {
        __syncthreads();
#pragma unroll
        for (int p = 0; p < 2; p++)
#pragma unroll
            for (int i = 0; i < 2; i++) {
                int u = t + (i << 8);
                int r = u >> 2, kq = (u & 3) << 3;
                *(uint4*)&sAm[p][r][kq] =
                    *(const uint4*)(A + (long long)p * planeA + (long long)(bm + r) * K + k0 + kq);
            }
        if (TRANSB) {
#pragma unroll
            for (int p = 0; p < 2; p++)
#pragma unroll
                for (int i = 0; i < 2; i++) {
                    int u = t + (i << 8);
                    int r = u >> 2, kq = (u & 3) << 3;
                    *(uint4*)&sBm[p][r * 40 + kq] =
                        *(const uint4*)(B + (long long)p * planeB + (long long)(bn + r) * K + k0 + kq);
                }
        } else {
#pragma unroll
            for (int p = 0; p < 2; p++)
#pragma unroll
                for (int i = 0; i < 2; i++) {
                    int u = t + (i << 8);
                    int kr = u >> 4, nq = (u & 15) << 3;
                    *(uint4*)&sBm[p][kr * 136 + nq] =
                        *(const uint4*)(B + (long long)p * planeB + (long long)(k0 + kr) * N + bn + nq);
                }
        }
        __syncthreads();

#pragma unroll
        for (int kk = 0; kk < 2; kk++) {
            uint32_t Af[4][4];
            uint32_t Bf[8];
            auto loadB = [&](int p) {
                if (TRANSB) {
                    uint32_t a0 = smem_u32(&sBm[p][(wn + ((lane >> 4) << 3) + (lane & 7)) * 40 + kk * 16 + (lane & 8)]);
                    asm volatile("ldmatrix.sync.aligned.m8n8.x4.shared.b16 {%0,%1,%2,%3}, [%4];"
                        : "=r"(Bf[0]), "=r"(Bf[1]), "=r"(Bf[2]), "=r"(Bf[3]) : "r"(a0));
                    uint32_t a1 = smem_u32(&sBm[p][(wn + 16 + ((lane >> 4) << 3) + (lane & 7)) * 40 + kk * 16 + (lane & 8)]);
                    asm volatile("ldmatrix.sync.aligned.m8n8.x4.shared.b16 {%0,%1,%2,%3}, [%4];"
                        : "=r"(Bf[4]), "=r"(Bf[5]), "=r"(Bf[6]), "=r"(Bf[7]) : "r"(a1));
                } else {
                    uint32_t a0 = smem_u32(&sBm[p][(kk * 16 + (lane & 7) + (lane & 8)) * 136 + wn + ((lane >> 4) << 3)]);
                    asm volatile("ldmatrix.sync.aligned.m8n8.x4.trans.shared.b16 {%0,%1,%2,%3}, [%4];"
                        : "=r"(Bf[0]), "=r"(Bf[1]), "=r"(Bf[2]), "=r"(Bf[3]) : "r"(a0));
                    uint32_t a1 = smem_u32(&sBm[p][(kk * 16 + (lane & 7) + (lane & 8)) * 136 + wn + 16 + ((lane >> 4) << 3)]);
                    asm volatile("ldmatrix.sync.aligned.m8n8.x4.trans.shared.b16 {%0,%1,%2,%3}, [%4];"
                        : "=r"(Bf[4]), "=r"(Bf[5]), "=r"(Bf[6]), "=r"(Bf[7]) : "r"(a1));
                }
            };
            auto loadA = [&](int p) {
#pragma unroll
                for (int mi = 0; mi < 4; mi++) {
                    uint32_t ad = smem_u32(&sAm[p][wm + mi * 16 + (lane & 15)][kk * 16 + ((lane >> 4) << 3)]);
                    asm volatile("ldmatrix.sync.aligned.m8n8.x4.shared.b16 {%0,%1,%2,%3}, [%4];"
                        : "=r"(Af[mi][0]), "=r"(Af[mi][1]), "=r"(Af[mi][2]), "=r"(Af[mi][3]) : "r"(ad));
                }
            };
            auto mmAll = [&]() {
#pragma unroll
                for (int mi = 0; mi < 4; mi++)
#pragma unroll
                    for (int nj = 0; nj < 4; nj++)
                        MMA(acc[mi][nj], Af[mi], Bf[2 * nj], Bf[2 * nj + 1]);
            };
            loadA(0); loadB(0); mmAll();
            loadB(1);           mmAll();
            loadA(1); loadB(0); mmAll();
        }
    }

#pragma unroll
    for (int mi = 0; mi < 4; mi++)
#pragma unroll
        for (int nj = 0; nj < 4; nj++) {
            int r0 = bm + wm + mi * 16 + (lane >> 2);
            int cc = bn + wn + nj * 8 + ((lane & 3) << 1);
            float2 bb = make_float2(0.f, 0.f);
            if (bias) bb = *(const float2*)(bias + cc);
#pragma unroll
            for (int h = 0; h < 2; h++) {
                long long off = (long long)(r0 + h * 8) * N + cc;
                float v0 = alpha * acc[mi][nj][2 * h + 0] + bb.x;
                float v1 = alpha * acc[mi][nj][2 * h + 1] + bb.y;
                if (WB16) {
                    float l0, l1;
                    *(uint32_t*)(Cb + off) = pack_hi2(v0, v1, l0, l1);
                    *(uint32_t*)(Cb + planeC + off) = pack2(l0, l1);
                } else {
                    *(float2*)(Cf + off) = make_float2(v0, v1);
                }
            }
        }
}

// ---------------------------------------------------------------------------
// Fused complex HMMA GEMM with Gauss 3-product option (BK=16).
//   P1 = Ar*Br, P2 = Ai*Bi, P3 = As*Bs.
//   GAUSS:  Re = P1 + s2*P2, Im = P3 - P1 + s2*P2 (s2=+1 CONJ with Bs=diff).
//   !GAUSS: A (!HAS_AI): Re=P1, Im=Ar*Bi;  D (!HAS_BI): Re=P1, Im=Ai*Br;
//           F (AI&BI,!WANT_I): Re = P1 - P2.
//   Pitch 24 bf16 = 48B rows (16B-aligned for cp.async/ldmatrix).
// ---------------------------------------------------------------------------
#define APL2 6144                 // 128*24*2 bytes per plane (BK=16)
#define BPL2_NT 6144
#define BPL2_NN 4352              // 16*136*2
#define TPITCH 132

template<bool TRANSB, bool CONJ, bool GAUSS, bool HAS_AI, bool HAS_BI,
         bool WANT_I, bool WF32, bool HERM, bool EMIT_S, bool EMIT_D>
__global__ __launch_bounds__(256, 1)
void cgemm_kernel(const bf16* __restrict__ Ar, const bf16* __restrict__ Ai,
                  const bf16* __restrict__ As, long long planeA,
                  const bf16* __restrict__ Br, const bf16* __restrict__ Bi,
                  const bf16* __restrict__ Bs, long long planeB,
                  float* __restrict__ CrF, float* __restrict__ CiF,
                  bf16* __restrict__ CrB, bf16* __restrict__ CiB,
                  bf16* __restrict__ CsB, bf16* __restrict__ CdB, long long planeC,
                  const float* __restrict__ biasR, const float* __restrict__ biasI,
                  int M, int N, int K,
                  long long sA, long long sB, long long sC,
                  float alpha)
{
    extern __shared__ __align__(16) char smem[];
    constexpr int NPA = 2 + (HAS_AI ? 2 : 0) + (GAUSS ? 2 : 0);
    constexpr int NPB = 2 + (HAS_BI ? 2 : 0) + (GAUSS ? 2 : 0);
    constexpr int BPL = TRANSB ? BPL2_NT : BPL2_NN;
    constexpr int ASZ = NPA * APL2;
    constexpr int STG = ASZ + NPB * BPL;

    const long long zb = blockIdx.z;
    Ar += zb * sA; if (HAS_AI) Ai += zb * sA; if (GAUSS) As += zb * sA;
    Br += zb * sB; if (HAS_BI) Bi += zb * sB; if (GAUSS) Bs += zb * sB;

    int bi, bj;
    if (HERM) {
        int bx = blockIdx.x;
        bi = (int)((sqrtf(8.f * bx + 1.f) - 1.f) * 0.5f);
        while ((bi + 1) * (bi + 2) / 2 <= bx) bi++;
        while (bi * (bi + 1) / 2 > bx) bi--;
        bj = bx - bi * (bi + 1) / 2;
    } else {
        bi = blockIdx.y; bj = blockIdx.x;
    }
    const int bm = bi * 128;
    const int bn = bj * 128;
    const int t = threadIdx.x, wid = t >> 5, lane = t & 31;
    const int wm = (wid >> 2) * 64, wn = (wid & 3) * 32;

    const uint32_t sbase = smem_u32(smem);

    const bf16* aps[6];
    aps[0] = Ar; aps[1] = Ar + planeA;
    if (HAS_AI) { aps[2] = Ai; aps[3] = Ai + planeA; }
    if (GAUSS)  { aps[4] = As; aps[5] = As + planeA; }
    const bf16* bps[6];
    bps[0] = Br; bps[1] = Br + planeB;
    if (HAS_BI) { bps[2] = Bi; bps[3] = Bi + planeB; }
    if (GAUSS)  { bps[4] = Bs; bps[5] = Bs + planeB; }

    auto issue = [&](int c, int buf) {
        const int k0 = c << 4;
        const uint32_t stg = sbase + (uint32_t)buf * STG;
        const int r = t >> 1, cq = (t & 1) << 3;
#pragma unroll
        for (int p = 0; p < NPA; p++)
            cp16(stg + p * APL2 + (r * 24 + cq) * 2,
                 aps[p] + (long long)(bm + r) * K + k0 + cq);
        if (TRANSB) {
#pragma unroll
            for (int p = 0; p < NPB; p++)
                cp16(stg + ASZ + p * BPL + (r * 24 + cq) * 2,
                     bps[p] + (long long)(bn + r) * K + k0 + cq);
        } else {
            const int kr = t >> 4, nq = (t & 15) << 3;
#pragma unroll
            for (int p = 0; p < NPB; p++)
                cp16(stg + ASZ + p * BPL + (kr * 136 + nq) * 2,
                     bps[p] + (long long)(k0 + kr) * N + bn + nq);
        }
        CP_COMMIT();
    };

    float a1[4][4][4], a2[4][4][4], a3[4][4][4];
#pragma unroll
    for (int a = 0; a < 4; a++)
#pragma unroll
        for (int b = 0; b < 4; b++)
#pragma unroll
            for (int c = 0; c < 4; c++) {
                a1[a][b][c] = 0.f; a2[a][b][c] = 0.f;
                if (GAUSS) a3[a][b][c] = 0.f;
            }

    const int nch = K >> 4;
    issue(0, 0);

    for (int c = 0; c < nch; c++) {
        const int buf = c & 1;
        if (c + 1 < nch) { issue(c + 1, buf ^ 1); CP_WAIT(1); }
        else             { CP_WAIT(0); }
        __syncthreads();

        bf16* sAp = (bf16*)(smem + buf * STG);
        bf16* sBp = (bf16*)(smem + buf * STG + ASZ);

        uint32_t Af[4][4], Bh[8], Bl[8];
        auto loadB = [&](int p, uint32_t* o) {
            bf16* bp = (bf16*)((char*)sBp + p * BPL);
            if (TRANSB) {
                uint32_t a0 = smem_u32(&bp[(wn + ((lane >> 4) << 3) + (lane & 7)) * 24 + (lane & 8)]);
                asm volatile("ldmatrix.sync.aligned.m8n8.x4.shared.b16 {%0,%1,%2,%3}, [%4];"
                    : "=r"(o[0]), "=r"(o[1]), "=r"(o[2]), "=r"(o[3]) : "r"(a0));
                uint32_t a1a = smem_u32(&bp[(wn + 16 + ((lane >> 4) << 3) + (lane & 7)) * 24 + (lane & 8)]);
                asm volatile("ldmatrix.sync.aligned.m8n8.x4.shared.b16 {%0,%1,%2,%3}, [%4];"
                    : "=r"(o[4]), "=r"(o[5]), "=r"(o[6]), "=r"(o[7]) : "r"(a1a));
            } else {
                uint32_t a0 = smem_u32(&bp[((lane & 7) + (lane & 8)) * 136 + wn + ((lane >> 4) << 3)]);
                asm volatile("ldmatrix.sync.aligned.m8n8.x4.trans.shared.b16 {%0,%1,%2,%3}, [%4];"
                    : "=r"(o[0]), "=r"(o[1]), "=r"(o[2]), "=r"(o[3]) : "r"(a0));
                uint32_t a1a = smem_u32(&bp[((lane & 7) + (lane & 8)) * 136 + wn + 16 + ((lane >> 4) << 3)]);
                asm volatile("ldmatrix.sync.aligned.m8n8.x4.trans.shared.b16 {%0,%1,%2,%3}, [%4];"
                    : "=r"(o[4]), "=r"(o[5]), "=r"(o[6]), "=r"(o[7]) : "r"(a1a));
            }
        };
        auto loadA = [&](int p) {
            bf16* ap = (bf16*)((char*)sAp + p * APL2);
#pragma unroll
            for (int mi = 0; mi < 4; mi++) {
                uint32_t ad = smem_u32(&ap[(wm + mi * 16 + (lane & 15)) * 24 + ((lane >> 4) << 3)]);
                asm volatile("ldmatrix.sync.aligned.m8n8.x4.shared.b16 {%0,%1,%2,%3}, [%4];"
                    : "=r"(Af[mi][0]), "=r"(Af[mi][1]), "=r"(Af[mi][2]), "=r"(Af[mi][3]) : "r"(ad));
            }
        };
        auto mmP = [&](float (*acc)[4][4], const uint32_t* b) {
#pragma unroll
            for (int mi = 0; mi < 4; mi++)
#pragma unroll
                for (int nj = 0; nj < 4; nj++)
                    MMA(acc[mi][nj], Af[mi], b[2 * nj], b[2 * nj + 1]);
        };

        // P1 = Ar * Br
        loadB(0, Bh); loadB(1, Bl);
        loadA(0); mmP(a1, Bh); mmP(a1, Bl);
        loadA(1); mmP(a1, Bh);
        if (GAUSS) {
            // P2 = Ai * Bi
            loadB(2, Bh); loadB(3, Bl);
            loadA(2); mmP(a2, Bh); mmP(a2, Bl);
            loadA(3); mmP(a2, Bh);
            // P3 = As * Bs
            loadB(4, Bh); loadB(5, Bl);
            loadA(4); mmP(a3, Bh); mmP(a3, Bl);
            loadA(5); mmP(a3, Bh);
        } else if (HAS_AI && HAS_BI) {      // config F: P2 = Ai*Bi
            loadB(2, Bh); loadB(3, Bl);
            loadA(2); mmP(a2, Bh); mmP(a2, Bl);
            loadA(3); mmP(a2, Bh);
        } else if (HAS_BI) {                // config A: P2 = Ar*Bi
            loadB(2, Bh); loadB(3, Bl);
            loadA(0); mmP(a2, Bh); mmP(a2, Bl);
            loadA(1); mmP(a2, Bh);
        } else if (HAS_AI) {                // config D: P2 = Ai*Br
            loadA(2); mmP(a2, Bh); mmP(a2, Bl);
            loadA(3); mmP(a2, Bh);
        }
        __syncthreads();
    }

    // ---- epilogue ----
    float* crf = WF32 ? CrF + zb * sC : nullptr;
    float* cif = (WF32 && WANT_I) ? CiF + zb * sC : nullptr;
    bf16*  crb = (!WF32) ? CrB + zb * sC : nullptr;
    bf16*  cib = (!WF32 && WANT_I) ? CiB + zb * sC : nullptr;
    bf16*  csb = (!WF32 && EMIT_S) ? CsB + zb * sC : nullptr;
    bf16*  cdb = (!WF32 && EMIT_D) ? CdB + zb * sC : nullptr;
    const bool mirror = HERM && (bi != bj);
    float* tsm = (float*)smem;

    auto combine = [&](float p1, float p2, float p3, float& re, float& im) {
        if (GAUSS) {
            const float s2 = CONJ ? 1.f : -1.f;
            re = p1 + s2 * p2;
            im = p3 - p1 + s2 * p2;
        } else if (HAS_AI && HAS_BI) {      // F
            re = p1 - p2; im = 0.f;
        } else {                            // A or D
            re = p1; im = p2;
        }
    };

#pragma unroll
    for (int mi = 0; mi < 4; mi++)
#pragma unroll
        for (int nj = 0; nj < 4; nj++) {
            int lr0 = wm + mi * 16 + (lane >> 2);
            int lc  = wn + nj * 8 + ((lane & 3) << 1);
            float bR0 = 0.f, bR1 = 0.f, bI0 = 0.f, bI1 = 0.f;
            if (biasR) { bR0 = biasR[bn + lc]; bR1 = biasR[bn + lc + 1]; }
            if (WANT_I && biasI) { bI0 = biasI[bn + lc]; bI1 = biasI[bn + lc + 1]; }
#pragma unroll
            for (int h = 0; h < 2; h++) {
                int lr = lr0 + h * 8;
                long long off = (long long)(bm + lr) * N + bn + lc;
                float re0, re1, im0, im1;
                combine(a1[mi][nj][2 * h], a2[mi][nj][2 * h],
                        GAUSS ? a3[mi][nj][2 * h] : 0.f, re0, im0);
                combine(a1[mi][nj][2 * h + 1], a2[mi][nj][2 * h + 1],
                        GAUSS ? a3[mi][nj][2 * h + 1] : 0.f, re1, im1);
                re0 = alpha * re0 + bR0; re1 = alpha * re1 + bR1;
                im0 = alpha * im0 + bI0; im1 = alpha * im1 + bI1;
                if (WF32) {
                    *(float2*)(crf + off) = make_float2(re0, re1);
                    if (WANT_I) *(float2*)(cif + off) = make_float2(im0, im1);
                    if (mirror) {
                        tsm[lc * TPITCH + lr] = re0;
                        tsm[(lc + 1) * TPITCH + lr] = re1;
                    }
                } else {
                    float l0, l1;
                    *(uint32_t*)(crb + off) = pack_hi2(re0, re1, l0, l1);
                    *(uint32_t*)(crb + planeC + off) = pack2(l0, l1);
                    if (WANT_I) {
                        *(uint32_t*)(cib + off) = pack_hi2(im0, im1, l0, l1);
                        *(uint32_t*)(cib + planeC + off) = pack2(l0, l1);
                    }
                    if (EMIT_S) {
                        *(uint32_t*)(csb + off) = pack_hi2(re0 + im0, re1 + im1, l0, l1);
                        *(uint32_t*)(csb + planeC + off) = pack2(l0, l1);
                    }
                    if (EMIT_D) {
                        *(uint32_t*)(cdb + off) = pack_hi2(re0 - im0, re1 - im1, l0, l1);
                        *(uint32_t*)(cdb + planeC + off) = pack2(l0, l1);
                    }
                }
            }
        }

    if (WF32 && mirror) {
        __syncthreads();
        {
            int rr = t >> 1, ch = (t & 1) * 64;
            long long orow = (long long)(bn + rr) * N + bm + ch;
#pragma unroll
            for (int j = 0; j < 64; j += 4)
                *(float4*)(crf + orow + j) = *(float4*)&tsm[rr * TPITCH + ch + j];
        }
        if (WANT_I) {
            __syncthreads();
#pragma unroll
            for (int mi = 0; mi < 4; mi++)
#pragma unroll
                for (int nj = 0; nj < 4; nj++) {
                    int lr0 = wm + mi * 16 + (lane >> 2);
                    int lc  = wn + nj * 8 + ((lane & 3) << 1);
#pragma unroll
                    for (int h = 0; h < 2; h++) {
                        int lr = lr0 + h * 8;
                        float re0, re1, im0, im1;
                        combine(a1[mi][nj][2 * h], a2[mi][nj][2 * h],
                                GAUSS ? a3[mi][nj][2 * h] : 0.f, re0, im0);
                        combine(a1[mi][nj][2 * h + 1], a2[mi][nj][2 * h + 1],
                                GAUSS ? a3[mi][nj][2 * h + 1] : 0.f, re1, im1);
                        tsm[lc * TPITCH + lr]       = -alpha * im0;
                        tsm[(lc + 1) * TPITCH + lr] = -alpha * im1;
                    }
                }
            __syncthreads();
            int rr = t >> 1, ch = (t & 1) * 64;
            long long orow = (long long)(bn + rr) * N + bm + ch;
#pragma unroll
            for (int j = 0; j < 64; j += 4)
                *(float4*)(cif + orow + j) = *(float4*)&tsm[rr * TPITCH + ch + j];
        }
    }
}

// ---------------------------------------------------------------------------
// Complex softmax: fp32 (sr,si) in, bf16 hi/lo planes (wr, wi, ws) out.
// ---------------------------------------------------------------------------
__global__ __launch_bounds__(256)
void csoftmax_kernel(const float* __restrict__ sr, const float* __restrict__ si,
                     bf16* __restrict__ osr, bf16* __restrict__ osi,
                     bf16* __restrict__ oss, long long plane)
{
    const long long row = blockIdx.x;
    const float* pr = sr + row * (long long)SEQ;
    const float* pi = si + row * (long long)SEQ;
    const int t = threadIdx.x;
    const int i0 = t * 8;

    float vr[8], vi[8], mag[8], e[8];
    *(float4*)&vr[0] = *(const float4*)(pr + i0);
    *(float4*)&vr[4] = *(const float4*)(pr + i0 + 4);
    *(float4*)&vi[0] = *(const float4*)(pi + i0);
    *(float4*)&vi[4] = *(const float4*)(pi + i0 + 4);

    float mx = -1e30f;
#pragma unroll
    for (int i = 0; i < 8; i++) {
        mag[i] = sqrtf(vr[i] * vr[i] + vi[i] * vi[i]);
        mx = fmaxf(mx, mag[i]);
    }
    __shared__ float red[256];
    red[t] = mx; __syncthreads();
#pragma unroll
    for (int s = 128; s > 0; s >>= 1) {
        if (t < s) red[t] = fmaxf(red[t], red[t + s]);
        __syncthreads();
    }
    mx = red[0];
    __syncthreads();
    float sum = 0.f;
#pragma unroll
    for (int i = 0; i < 8; i++) { e[i] = expf(mag[i] - mx); sum += e[i]; }
    red[t] = sum; __syncthreads();
#pragma unroll
    for (int s = 128; s > 0; s >>= 1) {
        if (t < s) red[t] += red[t + s];
        __syncthreads();
    }
    sum = red[0];
    const float inv_s = 1.0f / (sum + 1e-8f);

    float orv[8], oiv[8];
#pragma unroll
    for (int i = 0; i < 8; i++) {
        float f = e[i] * inv_s / (mag[i] + 1e-8f);
        orv[i] = vr[i] * f; oiv[i] = vi[i] * f;
    }
    long long off = row * (long long)SEQ + i0;
    uint4 h, l;
    float r0, r1;
    h.x = pack_hi2(orv[0], orv[1], r0, r1); l.x = pack2(r0, r1);
    h.y = pack_hi2(orv[2], orv[3], r0, r1); l.y = pack2(r0, r1);
    h.z = pack_hi2(orv[4], orv[5], r0, r1); l.z = pack2(r0, r1);
    h.w = pack_hi2(orv[6], orv[7], r0, r1); l.w = pack2(r0, r1);
    *(uint4*)(osr + off) = h;
    *(uint4*)(osr + plane + off) = l;
    h.x = pack_hi2(oiv[0], oiv[1], r0, r1); l.x = pack2(r0, r1);
    h.y = pack_hi2(oiv[2], oiv[3], r0, r1); l.y = pack2(r0, r1);
    h.z = pack_hi2(oiv[4], oiv[5], r0, r1); l.z = pack2(r0, r1);
    h.w = pack_hi2(oiv[6], oiv[7], r0, r1); l.w = pack2(r0, r1);
    *(uint4*)(osi + off) = h;
    *(uint4*)(osi + plane + off) = l;
    h.x = pack_hi2(orv[0] + oiv[0], orv[1] + oiv[1], r0, r1); l.x = pack2(r0, r1);
    h.y = pack_hi2(orv[2] + oiv[2], orv[3] + oiv[3], r0, r1); l.y = pack2(r0, r1);
    h.z = pack_hi2(orv[4] + oiv[4], orv[5] + oiv[5], r0, r1); l.z = pack2(r0, r1);
    h.w = pack_hi2(orv[6] + oiv[6], orv[7] + oiv[7], r0, r1); l.w = pack2(r0, r1);
    *(uint4*)(oss + off) = h;
    *(uint4*)(oss + plane + off) = l;
}

// Mf = 0.9*I + 0.1*flow_W  -> bf16 hi/lo planes directly
__global__ void build_mflow_kernel(const float* __restrict__ fw, bf16* __restrict__ mf,
                                   long long plane)
{
    int i = blockIdx.y * blockDim.y + threadIdx.y;
    int j = blockIdx.x * blockDim.x + threadIdx.x;
    float v = 0.1f * fw[(long long)i * MAN + j];
    if (i == j) v += 0.9f;
    bf16 h = __float2bfloat16(v);
    mf[(long long)i * MAN + j] = h;
    mf[plane + (long long)i * MAN + j] = __float2bfloat16(v - __bfloat162float(h));
}

// ---------------------------------------------------------------------------
// host-side
// ---------------------------------------------------------------------------
static void conv(const float* s, bf16* d, long long n)
{
    long long n4 = n / 4;
    convert_hilo_kernel<<<(unsigned)((n4 + 255) / 256), 256>>>(s, d, n4, n);
}
static void conv_sum(const float* a, const float* b, bf16* d, long long n)
{
    long long n4 = n / 4;
    convert_hilo_sum_kernel<<<(unsigned)((n4 + 255) / 256), 256>>>(a, b, d, n4, n);
}
static void hgemm_b16(bool transb, const bf16* A, long long pA, const bf16* B, long long pB,
                      bf16* C, long long pC, const float* bias, int M, int N, int K)
{
    dim3 grid(N / 128, M / 128, 1);
    if (transb) hgemm_kernel<true, true><<<grid, 256>>>(A, B, nullptr, C, pC, bias, M, N, K, pA, pB, 1.f);
    else        hgemm_kernel<false, true><<<grid, 256>>>(A, B, nullptr, C, pC, bias, M, N, K, pA, pB, 1.f);
}
static void hgemm_f32_nn(const bf16* A, long long pA, const bf16* B, long long pB,
                         float* C, const float* bias, int M, int N, int K)
{
    dim3 grid(N / 128, M / 128, 1);
    hgemm_kernel<false, false><<<grid, 256>>>(A, B, C, nullptr, 0, bias, M, N, K, pA, pB, 1.f);
}

// cgemm instantiation smem sizes (pitch-24 planes)
#define SM_A 73728      // 2*(2*6144 + 4*6144)
#define SM_B 147456     // 2*(6*6144 + 6*6144)
#define SM_C 147456
#define SM_D 66560      // 2*(4*6144 + 2*4352)
#define SM_E 125952     // 2*(6*6144 + 6*4352)
#define SM_F 83968      // 2*(4*6144 + 4*4352)

#define CG_A cgemm_kernel<true,  false, false, false, true,  true,  false, false, true,  true>
#define CG_B cgemm_kernel<true,  false, true,  true,  true,  true,  false, false, true,  true>
#define CG_C cgemm_kernel<true,  true,  true,  true,  true,  true,  true,  true,  false, false>
#define CG_D cgemm_kernel<false, false, false, true,  false, true,  false, false, true,  false>
#define CG_E cgemm_kernel<false, false, true,  true,  true,  true,  false, false, true,  false>
#define CG_F cgemm_kernel<false, false, false, true,  true,  false, false, false, false, false>

extern "C" void kernel_launch(void* const* d_in, const int* in_sizes, int n_in,
                              void* d_out, int out_size)
{
    const float* x      = (const float*)d_in[0];
    const float* Wp     = (const float*)d_in[1];
    const float* bp     = (const float*)d_in[2];
    const float* Wpinv  = (const float*)d_in[3];
    const float* bpinv  = (const float*)d_in[4];
    const float* aWr    = (const float*)d_in[5];
    const float* aWi    = (const float*)d_in[6];
    const float* abr    = (const float*)d_in[7];
    const float* abi    = (const float*)d_in[8];
    const float* metric = (const float*)d_in[9];
    const float* flowW  = (const float*)d_in[10];
    float* out = (float*)d_out;

    float *sr, *si;
    cudaGetSymbolAddress((void**)&sr, g_sr);
    cudaGetSymbolAddress((void**)&si, g_si);

    bf16 *cx, *cwp, *cwpinv, *cwr, *cwi, *cwsum, *cmet, *cm0, *cm1, *cm2, *ccpost;
    bf16 *cq0r, *cq0i, *cq0s, *cq1r, *cq1i, *cq1s;
    bf16 *car, *cai, *cas, *cad, *csr, *csi, *css;
    cudaGetSymbolAddress((void**)&cx,     c_x);
    cudaGetSymbolAddress((void**)&cwp,    c_wp);
    cudaGetSymbolAddress((void**)&cwpinv, c_wpinv);
    cudaGetSymbolAddress((void**)&cwr,    c_wr);
    cudaGetSymbolAddress((void**)&cwi,    c_wi);
    cudaGetSymbolAddress((void**)&cwsum,  c_wsum);
    cudaGetSymbolAddress((void**)&cmet,   c_met);
    cudaGetSymbolAddress((void**)&cm0,    c_m0);
    cudaGetSymbolAddress((void**)&cm1,    c_m1);
    cudaGetSymbolAddress((void**)&cm2,    c_m2);
    cudaGetSymbolAddress((void**)&ccpost, c_cpost);
    cudaGetSymbolAddress((void**)&cq0r,   c_q0r);
    cudaGetSymbolAddress((void**)&cq0i,   c_q0i);
    cudaGetSymbolAddress((void**)&cq0s,   c_q0s);
    cudaGetSymbolAddress((void**)&cq1r,   c_q1r);
    cudaGetSymbolAddress((void**)&cq1i,   c_q1i);
    cudaGetSymbolAddress((void**)&cq1s,   c_q1s);
    cudaGetSymbolAddress((void**)&car,    c_ar);
    cudaGetSymbolAddress((void**)&cai,    c_ai);
    cudaGetSymbolAddress((void**)&cas,    c_as);
    cudaGetSymbolAddress((void**)&cad,    c_ad);
    cudaGetSymbolAddress((void**)&csr,    c_sr);
    cudaGetSymbolAddress((void**)&csi,    c_si);
    cudaGetSymbolAddress((void**)&css,    c_ss);

    cudaFuncSetAttribute(CG_A, cudaFuncAttributeMaxDynamicSharedMemorySize, SM_A);
    cudaFuncSetAttribute(CG_B, cudaFuncAttributeMaxDynamicSharedMemorySize, SM_B);
    cudaFuncSetAttribute(CG_C, cudaFuncAttributeMaxDynamicSharedMemorySize, SM_C);
    cudaFuncSetAttribute(CG_D, cudaFuncAttributeMaxDynamicSharedMemorySize, SM_D);
    cudaFuncSetAttribute(CG_E, cudaFuncAttributeMaxDynamicSharedMemorySize, SM_E);
    cudaFuncSetAttribute(CG_F, cudaFuncAttributeMaxDynamicSharedMemorySize, SM_F);

    const float scale = 0.03125f;                 // 1/sqrt(1024)
    const long long sQ = (long long)SEQ * MAN;
    const long long sS = (long long)SEQ * SEQ;
    const long long pMM = (long long)MAN * MAN;
    const long long pQ  = (long long)ROWS * MAN;
    const long long pS  = (long long)BATCH * SEQ * SEQ;

    // ---- converts ----
    conv(x, cx, (long long)ROWS * HID);
    conv(Wp, cwp, (long long)MAN * HID);
    conv(aWr, cwr, pMM);
    conv(aWi, cwi, pMM);

    // ---- projection qr = x @ Wp^T + bp (bf16 planes) ----
    hgemm_b16(true, cx, (long long)ROWS * HID, cwp, (long long)MAN * HID,
              cq0r, pQ, bp, ROWS, MAN, HID);

    bf16 *qr = cq0r, *qi = cq0i, *qs = cq0s;
    bf16 *nqr = cq1r, *nqi = cq1i, *nqs = cq1s;

    for (int l = 0; l < NLAYERS; l++) {
        if (l > 0) {
            conv(aWr + (long long)l * pMM, cwr, pMM);
            conv(aWi + (long long)l * pMM, cwi, pMM);
            conv_sum(aWr + (long long)l * pMM, aWi + (long long)l * pMM, cwsum, pMM);
        }
        const float* br = abr + (long long)l * MAN;
        const float* bi = abi + (long long)l * MAN;

        // a = q (*) W^T + b  -> ar, ai, as(=r+i), ad(=r-i) planes
        {
            dim3 grid(MAN / 128, ROWS / 128, 1);
            if (l == 0)
                CG_A<<<grid, 256, SM_A>>>(
                    qr, nullptr, nullptr, pQ, cwr, cwi, nullptr, pMM,
                    nullptr, nullptr, car, cai, cas, cad, pQ, br, bi,
                    ROWS, MAN, MAN, 0, 0, 0, 1.f);
            else
                CG_B<<<grid, 256, SM_B>>>(
                    qr, qi, qs, pQ, cwr, cwi, cwsum, pMM,
                    nullptr, nullptr, car, cai, cas, cad, pQ, br, bi,
                    ROWS, MAN, MAN, 0, 0, 0, 1.f);
        }

        // scores = scale * a (*) conj(a)^T  (Gauss: B-sum plane = ad)
        {
            dim3 grid(136, 1, BATCH);
            CG_C<<<grid, 256, SM_C>>>(
                car, cai, cas, pQ, car, cai, cad, pQ,
                sr, si, nullptr, nullptr, nullptr, nullptr, pS, nullptr, nullptr,
                SEQ, SEQ, MAN, sQ, sQ, sS, scale);
        }

        csoftmax_kernel<<<BATCH * SEQ, 256>>>(sr, si, csr, csi, css, pS);

        // q' = attn (*) q
        {
            dim3 grid(MAN / 128, SEQ / 128, BATCH);
            if (l == 0)
                CG_D<<<grid, 256, SM_D>>>(
                    csr, csi, nullptr, pS, qr, nullptr, nullptr, pQ,
                    nullptr, nullptr, nqr, nqi, nqs, nullptr, pQ, nullptr, nullptr,
                    SEQ, MAN, SEQ, sS, sQ, sQ, 1.f);
            else if (l < NLAYERS - 1)
                CG_E<<<grid, 256, SM_E>>>(
                    csr, csi, css, pS, qr, qi, qs, pQ,
                    nullptr, nullptr, nqr, nqi, nqs, nullptr, pQ, nullptr, nullptr,
                    SEQ, MAN, SEQ, sS, sQ, sQ, 1.f);
            else
                CG_F<<<grid, 256, SM_F>>>(
                    csr, csi, nullptr, pS, qr, qi, nullptr, pQ,
                    nullptr, nullptr, nqr, nullptr, nullptr, nullptr, pQ, nullptr, nullptr,
                    SEQ, MAN, SEQ, sS, sQ, sQ, 1.f);
        }

        bf16* tt;
        tt = qr; qr = nqr; nqr = tt;
        tt = qi; qi = nqi; nqi = tt;
        tt = qs; qs = nqs; nqs = tt;
    }

    // ---- setup chain: cpost = metric * Mf^10 * Wpinv^T ----
    conv(metric, cmet, pMM);
    conv(Wpinv, cwpinv, (long long)HID * MAN);
    {
        dim3 blk(16, 16), grd(MAN / 16, MAN / 16);
        build_mflow_kernel<<<grd, blk>>>(flowW, cm0, pMM);
    }
    hgemm_b16(false, cm0, pMM, cm0, pMM, cm1, pMM, nullptr, MAN, MAN, MAN);   // Mf^2
    hgemm_b16(false, cm1, pMM, cm1, pMM, cm2, pMM, nullptr, MAN, MAN, MAN);   // Mf^4
    hgemm_b16(false, cm2, pMM, cm2, pMM, cm0, pMM, nullptr, MAN, MAN, MAN);   // Mf^8
    hgemm_b16(false, cm0, pMM, cm1, pMM, cm2, pMM, nullptr, MAN, MAN, MAN);   // Mf^10
    hgemm_b16(false, cmet, pMM, cm2, pMM, cm1, pMM, nullptr, MAN, MAN, MAN);  // g*Mf^10
    hgemm_b16(true, cm1, pMM, cwpinv, (long long)HID * MAN, ccpost,
              (long long)MAN * HID, nullptr, MAN, HID, MAN);                  // * Wpinv^T

    // ---- out = Re(q) @ Cpost + bp_inv ----
    hgemm_f32_nn(qr, pQ, ccpost, (long long)MAN * HID, out, bpinv, ROWS, HID, MAN);
}

// round 10
// speedup vs baseline: 1.1363x; 1.1363x over previous
#include <cuda_runtime.h>
#include <cuda_bf16.h>
#include <stdint.h>
#include <math.h>

// ---------------------------------------------------------------------------
// QuantumGeometricAttention forward.  Fused complex HMMA GEMMs, bf16 hi/lo
// split (3 passes per real product), cp.async double buffering (BK=32),
// Hermitian scores: fp32 out + SMEM-transposed coalesced conjugate mirror.
// ---------------------------------------------------------------------------

#define BATCH 2
#define SEQ   2048
#define HID   1024
#define MAN   1024
#define ROWS  (BATCH * SEQ)
#define NLAYERS 3

typedef __nv_bfloat16 bf16;

// ---------------- fp32 scratch ----------------------------------------------
__device__ float g_sr [(size_t)BATCH * SEQ * SEQ];
__device__ float g_si [(size_t)BATCH * SEQ * SEQ];

// ---------------- bf16 hi/lo planes (hi at 0, lo at +plane) ------------------
__device__ bf16 c_x    [2 * (size_t)ROWS * HID];
__device__ bf16 c_wp   [2 * (size_t)MAN * HID];
__device__ bf16 c_wpinv[2 * (size_t)HID * MAN];
__device__ bf16 c_wr   [(size_t)NLAYERS * 2 * MAN * MAN];
__device__ bf16 c_wi   [(size_t)NLAYERS * 2 * MAN * MAN];
__device__ bf16 c_met  [2 * (size_t)MAN * MAN];
__device__ bf16 c_m0   [2 * (size_t)MAN * MAN];
__device__ bf16 c_m1   [2 * (size_t)MAN * MAN];
__device__ bf16 c_m2   [2 * (size_t)MAN * MAN];
__device__ bf16 c_cpost[2 * (size_t)MAN * HID];
__device__ bf16 c_q0r  [2 * (size_t)ROWS * MAN];
__device__ bf16 c_q0i  [2 * (size_t)ROWS * MAN];
__device__ bf16 c_q1r  [2 * (size_t)ROWS * MAN];
__device__ bf16 c_q1i  [2 * (size_t)ROWS * MAN];
__device__ bf16 c_ar   [2 * (size_t)ROWS * MAN];
__device__ bf16 c_ai   [2 * (size_t)ROWS * MAN];
__device__ bf16 c_sr   [2 * (size_t)BATCH * SEQ * SEQ];
__device__ bf16 c_si   [2 * (size_t)BATCH * SEQ * SEQ];

// ---------------------------- helpers ---------------------------------------
__device__ __forceinline__ uint32_t smem_u32(const void* p) {
    uint32_t a;
    asm("{ .reg .u64 t; cvta.to.shared.u64 t, %1; cvt.u32.u64 %0, t; }" : "=r"(a) : "l"(p));
    return a;
}
__device__ __forceinline__ void cp16(uint32_t dst, const void* src) {
    asm volatile("{ .reg .u64 g; cvta.to.global.u64 g, %1; cp.async.cg.shared.global [%0], [g], 16; }"
                 :: "r"(dst), "l"(src) : "memory");
}
#define CP_COMMIT() asm volatile("cp.async.commit_group;" ::: "memory")
#define CP_WAIT(n)  asm volatile("cp.async.wait_group %0;" :: "n"(n) : "memory")

#define MMA(d, a, b0, b1) \
    asm volatile("mma.sync.aligned.m16n8k16.row.col.f32.bf16.bf16.f32 " \
        "{%0,%1,%2,%3}, {%4,%5,%6,%7}, {%8,%9}, {%0,%1,%2,%3};" \
        : "+f"((d)[0]), "+f"((d)[1]), "+f"((d)[2]), "+f"((d)[3]) \
        : "r"((a)[0]), "r"((a)[1]), "r"((a)[2]), "r"((a)[3]), "r"(b0), "r"(b1))

__device__ __forceinline__ uint32_t pack_hi2(float a, float b, float& ra, float& rb) {
    bf16 h0 = __float2bfloat16(a), h1 = __float2bfloat16(b);
    ra = a - __bfloat162float(h0); rb = b - __bfloat162float(h1);
    return (uint32_t)__bfloat16_as_ushort(h0) | ((uint32_t)__bfloat16_as_ushort(h1) << 16);
}
__device__ __forceinline__ uint32_t pack2(float a, float b) {
    return (uint32_t)__bfloat16_as_ushort(__float2bfloat16(a)) |
           ((uint32_t)__bfloat16_as_ushort(__float2bfloat16(b)) << 16);
}

// ---------------------------------------------------------------------------
// fp32 -> bf16 hi/lo convert
// ---------------------------------------------------------------------------
__global__ __launch_bounds__(256)
void convert_hilo_kernel(const float* __restrict__ src, bf16* __restrict__ dst,
                         long long n4, long long plane)
{
    long long i = (long long)blockIdx.x * blockDim.x + threadIdx.x;
    if (i >= n4) return;
    float4 v = ((const float4*)src)[i];
    float r0, r1, r2, r3;
    uint2 hp, lp;
    hp.x = pack_hi2(v.x, v.y, r0, r1);
    hp.y = pack_hi2(v.z, v.w, r2, r3);
    lp.x = pack2(r0, r1);
    lp.y = pack2(r2, r3);
    ((uint2*)dst)[i] = hp;
    ((uint2*)(dst + plane))[i] = lp;
}

// ---------------------------------------------------------------------------
// Real HMMA GEMM (BK=32), bf16 hi/lo 3-pass; writes fp32 or bf16 planes.
// ---------------------------------------------------------------------------
template<bool TRANSB, bool WB16>
__global__ __launch_bounds__(256, 2)
void hgemm_kernel(const bf16* __restrict__ A, const bf16* __restrict__ B,
                  float* __restrict__ Cf, bf16* __restrict__ Cb, long long planeC,
                  const float* __restrict__ bias,
                  int M, int N, int K,
                  long long planeA, long long planeB,
                  float alpha)
{
    __shared__ __align__(16) bf16 sAm[2][128][40];
    __shared__ __align__(16) bf16 sBm[2][5120];

    const int bm = blockIdx.y * 128;
    const int bn = blockIdx.x * 128;
    const int t = threadIdx.x, wid = t >> 5, lane = t & 31;
    const int wm = (wid >> 2) * 64, wn = (wid & 3) * 32;

    float acc[4][4][4];
#pragma unroll
    for (int a = 0; a < 4; a++)
#pragma unroll
        for (int b = 0; b < 4; b++)
#pragma unroll
            for (int c = 0; c < 4; c++) acc[a][b][c] = 0.f;

    for (int k0 = 0; k0 < K; k0 += 32) {
        __syncthreads();
#pragma unroll
        for (int p = 0; p < 2; p++)
#pragma unroll
            for (int i = 0; i < 2; i++) {
                int u = t + (i << 8);
                int r = u >> 2, kq = (u & 3) << 3;
                *(uint4*)&sAm[p][r][kq] =
                    *(const uint4*)(A + (long long)p * planeA + (long long)(bm + r) * K + k0 + kq);
            }
        if (TRANSB) {
#pragma unroll
            for (int p = 0; p < 2; p++)
#pragma unroll
                for (int i = 0; i < 2; i++) {
                    int u = t + (i << 8);
                    int r = u >> 2, kq = (u & 3) << 3;
                    *(uint4*)&sBm[p][r * 40 + kq] =
                        *(const uint4*)(B + (long long)p * planeB + (long long)(bn + r) * K + k0 + kq);
                }
        } else {
#pragma unroll
            for (int p = 0; p < 2; p++)
#pragma unroll
                for (int i = 0; i < 2; i++) {
                    int u = t + (i << 8);
                    int kr = u >> 4, nq = (u & 15) << 3;
                    *(uint4*)&sBm[p][kr * 136 + nq] =
                        *(const uint4*)(B + (long long)p * planeB + (long long)(k0 + kr) * N + bn + nq);
                }
        }
        __syncthreads();

#pragma unroll
        for (int kk = 0; kk < 2; kk++) {
            uint32_t Af[4][4];
            uint32_t Bf[8];
            auto loadB = [&](int p) {
                if (TRANSB) {
                    uint32_t a0 = smem_u32(&sBm[p][(wn + ((lane >> 4) << 3) + (lane & 7)) * 40 + kk * 16 + (lane & 8)]);
                    asm volatile("ldmatrix.sync.aligned.m8n8.x4.shared.b16 {%0,%1,%2,%3}, [%4];"
                        : "=r"(Bf[0]), "=r"(Bf[1]), "=r"(Bf[2]), "=r"(Bf[3]) : "r"(a0));
                    uint32_t a1 = smem_u32(&sBm[p][(wn + 16 + ((lane >> 4) << 3) + (lane & 7)) * 40 + kk * 16 + (lane & 8)]);
                    asm volatile("ldmatrix.sync.aligned.m8n8.x4.shared.b16 {%0,%1,%2,%3}, [%4];"
                        : "=r"(Bf[4]), "=r"(Bf[5]), "=r"(Bf[6]), "=r"(Bf[7]) : "r"(a1));
                } else {
                    uint32_t a0 = smem_u32(&sBm[p][(kk * 16 + (lane & 7) + (lane & 8)) * 136 + wn + ((lane >> 4) << 3)]);
                    asm volatile("ldmatrix.sync.aligned.m8n8.x4.trans.shared.b16 {%0,%1,%2,%3}, [%4];"
                        : "=r"(Bf[0]), "=r"(Bf[1]), "=r"(Bf[2]), "=r"(Bf[3]) : "r"(a0));
                    uint32_t a1 = smem_u32(&sBm[p][(kk * 16 + (lane & 7) + (lane & 8)) * 136 + wn + 16 + ((lane >> 4) << 3)]);
                    asm volatile("ldmatrix.sync.aligned.m8n8.x4.trans.shared.b16 {%0,%1,%2,%3}, [%4];"
                        : "=r"(Bf[4]), "=r"(Bf[5]), "=r"(Bf[6]), "=r"(Bf[7]) : "r"(a1));
                }
            };
            auto loadA = [&](int p) {
#pragma unroll
                for (int mi = 0; mi < 4; mi++) {
                    uint32_t ad = smem_u32(&sAm[p][wm + mi * 16 + (lane & 15)][kk * 16 + ((lane >> 4) << 3)]);
                    asm volatile("ldmatrix.sync.aligned.m8n8.x4.shared.b16 {%0,%1,%2,%3}, [%4];"
                        : "=r"(Af[mi][0]), "=r"(Af[mi][1]), "=r"(Af[mi][2]), "=r"(Af[mi][3]) : "r"(ad));
                }
            };
            auto mmAll = [&]() {
#pragma unroll
                for (int mi = 0; mi < 4; mi++)
#pragma unroll
                    for (int nj = 0; nj < 4; nj++)
                        MMA(acc[mi][nj], Af[mi], Bf[2 * nj], Bf[2 * nj + 1]);
            };
            loadA(0); loadB(0); mmAll();
            loadB(1);           mmAll();
            loadA(1); loadB(0); mmAll();
        }
    }

#pragma unroll
    for (int mi = 0; mi < 4; mi++)
#pragma unroll
        for (int nj = 0; nj < 4; nj++) {
            int r0 = bm + wm + mi * 16 + (lane >> 2);
            int cc = bn + wn + nj * 8 + ((lane & 3) << 1);
            float2 bb = make_float2(0.f, 0.f);
            if (bias) bb = *(const float2*)(bias + cc);
#pragma unroll
            for (int h = 0; h < 2; h++) {
                long long off = (long long)(r0 + h * 8) * N + cc;
                float v0 = alpha * acc[mi][nj][2 * h + 0] + bb.x;
                float v1 = alpha * acc[mi][nj][2 * h + 1] + bb.y;
                if (WB16) {
                    float l0, l1;
                    *(uint32_t*)(Cb + off) = pack_hi2(v0, v1, l0, l1);
                    *(uint32_t*)(Cb + planeC + off) = pack2(l0, l1);
                } else {
                    *(float2*)(Cf + off) = make_float2(v0, v1);
                }
            }
        }
}

// ---------------------------------------------------------------------------
// Fused complex HMMA GEMM (BK=32, 12 passes for full complex).
//   HERM: lower-triangular tiles; fp32 out + SMEM-transposed coalesced mirror.
// ---------------------------------------------------------------------------
#define APL 10240                 // 128*40*2 bytes per plane
#define BPL_NT 10240
#define BPL_NN 8704               // 32*136*2
#define TPITCH 132

template<bool TRANSB, bool CONJ, bool HAS_AI, bool HAS_BI, bool WANT_I,
         bool WF32, bool WB16, bool HERM>
__global__ __launch_bounds__(256, 1)
void cgemm_kernel(const bf16* __restrict__ Ar, const bf16* __restrict__ Ai, long long planeA,
                  const bf16* __restrict__ Br, const bf16* __restrict__ Bi, long long planeB,
                  float* __restrict__ CrF, float* __restrict__ CiF,
                  bf16* __restrict__ CrB, bf16* __restrict__ CiB, long long planeC,
                  const float* __restrict__ biasR, const float* __restrict__ biasI,
                  int M, int N, int K,
                  long long sA, long long sB, long long sC,
                  float alpha)
{
    extern __shared__ __align__(16) char smem[];
    constexpr int BPL = TRANSB ? BPL_NT : BPL_NN;
    constexpr int ASZ = 4 * APL;
    constexpr int STG = ASZ + 4 * BPL;

    const long long zb = blockIdx.z;
    Ar += zb * sA; if (HAS_AI) Ai += zb * sA;
    Br += zb * sB; if (HAS_BI) Bi += zb * sB;

    int bi, bj;
    if (HERM) {
        int bx = blockIdx.x;
        bi = (int)((sqrtf(8.f * bx + 1.f) - 1.f) * 0.5f);
        while ((bi + 1) * (bi + 2) / 2 <= bx) bi++;
        while (bi * (bi + 1) / 2 > bx) bi--;
        bj = bx - bi * (bi + 1) / 2;
    } else {
        bi = blockIdx.y; bj = blockIdx.x;
    }
    const int bm = bi * 128;
    const int bn = bj * 128;
    const int t = threadIdx.x, wid = t >> 5, lane = t & 31;
    const int wm = (wid >> 2) * 64, wn = (wid & 3) * 32;

    const uint32_t sbase = smem_u32(smem);
    const bf16* aps[4] = { Ar, Ar + planeA, Ai, HAS_AI ? (Ai + planeA) : Ai };
    const bf16* bps[4] = { Br, Br + planeB, Bi, HAS_BI ? (Bi + planeB) : Bi };
    const int NPA = HAS_AI ? 4 : 2;
    const int NPB = HAS_BI ? 4 : 2;

    auto issue = [&](int c, int buf) {
        const int k0 = c << 5;
        const uint32_t stg = sbase + (uint32_t)buf * STG;
        for (int p = 0; p < NPA; p++) {
#pragma unroll
            for (int i = 0; i < 2; i++) {
                int u = t + (i << 8);
                int r = u >> 2, cq = (u & 3) << 3;
                cp16(stg + p * APL + (r * 40 + cq) * 2,
                     aps[p] + (long long)(bm + r) * K + k0 + cq);
            }
        }
        if (TRANSB) {
            for (int p = 0; p < NPB; p++) {
#pragma unroll
                for (int i = 0; i < 2; i++) {
                    int u = t + (i << 8);
                    int r = u >> 2, cq = (u & 3) << 3;
                    cp16(stg + ASZ + p * BPL + (r * 40 + cq) * 2,
                         bps[p] + (long long)(bn + r) * K + k0 + cq);
                }
            }
        } else {
            for (int p = 0; p < NPB; p++) {
#pragma unroll
                for (int i = 0; i < 2; i++) {
                    int u = t + (i << 8);
                    int kr = u >> 4, nq = (u & 15) << 3;
                    cp16(stg + ASZ + p * BPL + (kr * 136 + nq) * 2,
                         bps[p] + (long long)(k0 + kr) * N + bn + nq);
                }
            }
        }
        CP_COMMIT();
    };

    float accR[4][4][4], accI[4][4][4];
#pragma unroll
    for (int a = 0; a < 4; a++)
#pragma unroll
        for (int b = 0; b < 4; b++)
#pragma unroll
            for (int c = 0; c < 4; c++) { accR[a][b][c] = 0.f; accI[a][b][c] = 0.f; }

    const int nch = K >> 5;
    issue(0, 0);

    for (int c = 0; c < nch; c++) {
        const int buf = c & 1;
        if (c + 1 < nch) { issue(c + 1, buf ^ 1); CP_WAIT(1); }
        else             { CP_WAIT(0); }
        __syncthreads();

        bf16* sAp = (bf16*)(smem + buf * STG);
        bf16* sBp = (bf16*)(smem + buf * STG + ASZ);

#pragma unroll
        for (int kk = 0; kk < 2; kk++) {
            uint32_t brh[8], brl[8], bih[8], bil[8];
            auto loadB = [&](int p, uint32_t* o) {
                bf16* bp = (bf16*)((char*)sBp + p * BPL);
                if (TRANSB) {
                    uint32_t a0 = smem_u32(&bp[(wn + ((lane >> 4) << 3) + (lane & 7)) * 40 + kk * 16 + (lane & 8)]);
                    asm volatile("ldmatrix.sync.aligned.m8n8.x4.shared.b16 {%0,%1,%2,%3}, [%4];"
                        : "=r"(o[0]), "=r"(o[1]), "=r"(o[2]), "=r"(o[3]) : "r"(a0));
                    uint32_t a1 = smem_u32(&bp[(wn + 16 + ((lane >> 4) << 3) + (lane & 7)) * 40 + kk * 16 + (lane & 8)]);
                    asm volatile("ldmatrix.sync.aligned.m8n8.x4.shared.b16 {%0,%1,%2,%3}, [%4];"
                        : "=r"(o[4]), "=r"(o[5]), "=r"(o[6]), "=r"(o[7]) : "r"(a1));
                } else {
                    uint32_t a0 = smem_u32(&bp[(kk * 16 + (lane & 7) + (lane & 8)) * 136 + wn + ((lane >> 4) << 3)]);
                    asm volatile("ldmatrix.sync.aligned.m8n8.x4.trans.shared.b16 {%0,%1,%2,%3}, [%4];"
                        : "=r"(o[0]), "=r"(o[1]), "=r"(o[2]), "=r"(o[3]) : "r"(a0));
                    uint32_t a1 = smem_u32(&bp[(kk * 16 + (lane & 7) + (lane & 8)) * 136 + wn + 16 + ((lane >> 4) << 3)]);
                    asm volatile("ldmatrix.sync.aligned.m8n8.x4.trans.shared.b16 {%0,%1,%2,%3}, [%4];"
                        : "=r"(o[4]), "=r"(o[5]), "=r"(o[6]), "=r"(o[7]) : "r"(a1));
                }
            };
            loadB(0, brh); loadB(1, brl);
            if (HAS_BI) { loadB(2, bih); loadB(3, bil); }

            uint32_t Af[4][4];
            auto loadA = [&](int p) {
                bf16* ap = (bf16*)((char*)sAp + p * APL);
#pragma unroll
                for (int mi = 0; mi < 4; mi++) {
                    uint32_t ad = smem_u32(&ap[(wm + mi * 16 + (lane & 15)) * 40 + kk * 16 + ((lane >> 4) << 3)]);
                    asm volatile("ldmatrix.sync.aligned.m8n8.x4.shared.b16 {%0,%1,%2,%3}, [%4];"
                        : "=r"(Af[mi][0]), "=r"(Af[mi][1]), "=r"(Af[mi][2]), "=r"(Af[mi][3]) : "r"(ad));
                }
            };
            auto negA = [&]() {
#pragma unroll
                for (int mi = 0; mi < 4; mi++)
#pragma unroll
                    for (int j = 0; j < 4; j++) Af[mi][j] ^= 0x80008000u;
            };
            auto mmP = [&](float (*acc)[4][4], const uint32_t* b) {
#pragma unroll
                for (int mi = 0; mi < 4; mi++)
#pragma unroll
                    for (int nj = 0; nj < 4; nj++)
                        MMA(acc[mi][nj], Af[mi], b[2 * nj], b[2 * nj + 1]);
            };

            loadA(0);
            mmP(accR, brh); mmP(accR, brl);
            if (WANT_I && HAS_BI) {
                if (CONJ) negA();
                mmP(accI, bih); mmP(accI, bil);
            }
            loadA(1);
            mmP(accR, brh);
            if (WANT_I && HAS_BI) { if (CONJ) negA(); mmP(accI, bih); }
            if (HAS_AI) {
                loadA(2);
                if (WANT_I) { mmP(accI, brh); mmP(accI, brl); }
                if (HAS_BI) {
                    if (!CONJ) negA();
                    mmP(accR, bih); mmP(accR, bil);
                }
                loadA(3);
                if (WANT_I) mmP(accI, brh);
                if (HAS_BI) { if (!CONJ) negA(); mmP(accR, bih); }
            }
        }
        __syncthreads();
    }

    // ---- epilogue ----
    float* crf = WF32 ? CrF + zb * sC : nullptr;
    float* cif = (WF32 && WANT_I) ? CiF + zb * sC : nullptr;
    bf16*  crb = WB16 ? CrB + zb * sC : nullptr;
    bf16*  cib = (WB16 && WANT_I) ? CiB + zb * sC : nullptr;
    const bool mirror = HERM && (bi != bj);
    float* tsm = (float*)smem;     // fp32 transpose staging (mirror only)

#pragma unroll
    for (int mi = 0; mi < 4; mi++)
#pragma unroll
        for (int nj = 0; nj < 4; nj++) {
            int lr0 = wm + mi * 16 + (lane >> 2);
            int lc  = wn + nj * 8 + ((lane & 3) << 1);
            float bR0 = 0.f, bR1 = 0.f, bI0 = 0.f, bI1 = 0.f;
            if (biasR) { bR0 = biasR[bn + lc]; bR1 = biasR[bn + lc + 1]; }
            if (WANT_I && biasI) { bI0 = biasI[bn + lc]; bI1 = biasI[bn + lc + 1]; }
#pragma unroll
            for (int h = 0; h < 2; h++) {
                int lr = lr0 + h * 8;
                long long off = (long long)(bm + lr) * N + bn + lc;
                float vr0 = alpha * accR[mi][nj][2 * h + 0] + bR0;
                float vr1 = alpha * accR[mi][nj][2 * h + 1] + bR1;
                float vi0 = 0.f, vi1 = 0.f;
                if (WANT_I) {
                    vi0 = alpha * accI[mi][nj][2 * h + 0] + bI0;
                    vi1 = alpha * accI[mi][nj][2 * h + 1] + bI1;
                }
                if (WF32) {
                    *(float2*)(crf + off) = make_float2(vr0, vr1);
                    if (WANT_I) *(float2*)(cif + off) = make_float2(vi0, vi1);
                    if (mirror) {
                        tsm[lc * TPITCH + lr] = vr0;
                        tsm[(lc + 1) * TPITCH + lr] = vr1;
                    }
                }
                if (WB16) {
                    float l0, l1;
                    *(uint32_t*)(crb + off) = pack_hi2(vr0, vr1, l0, l1);
                    *(uint32_t*)(crb + planeC + off) = pack2(l0, l1);
                    if (WANT_I) {
                        *(uint32_t*)(cib + off) = pack_hi2(vi0, vi1, l0, l1);
                        *(uint32_t*)(cib + planeC + off) = pack2(l0, l1);
                    }
                }
            }
        }

    if (WF32 && mirror) {
        // mirrored real tile via SMEM transpose -> coalesced fp32 row stores
        __syncthreads();
        {
            int rr = t >> 1, ch = (t & 1) * 64;
            long long orow = (long long)(bn + rr) * N + bm + ch;
#pragma unroll
            for (int j = 0; j < 64; j += 4)
                *(float4*)(crf + orow + j) = *(float4*)&tsm[rr * TPITCH + ch + j];
        }
        if (WANT_I) {
            __syncthreads();
#pragma unroll
            for (int mi = 0; mi < 4; mi++)
#pragma unroll
                for (int nj = 0; nj < 4; nj++) {
                    int lr0 = wm + mi * 16 + (lane >> 2);
                    int lc  = wn + nj * 8 + ((lane & 3) << 1);
#pragma unroll
                    for (int h = 0; h < 2; h++) {
                        int lr = lr0 + h * 8;
                        tsm[lc * TPITCH + lr]       = -alpha * accI[mi][nj][2 * h + 0];
                        tsm[(lc + 1) * TPITCH + lr] = -alpha * accI[mi][nj][2 * h + 1];
                    }
                }
            __syncthreads();
            int rr = t >> 1, ch = (t & 1) * 64;
            long long orow = (long long)(bn + rr) * N + bm + ch;
#pragma unroll
            for (int j = 0; j < 64; j += 4)
                *(float4*)(cif + orow + j) = *(float4*)&tsm[rr * TPITCH + ch + j];
        }
    }
}

// ---------------------------------------------------------------------------
// Complex softmax: fp32 (sr,si) in, bf16 hi/lo planes out.
// ---------------------------------------------------------------------------
__global__ __launch_bounds__(256)
void csoftmax_kernel(const float* __restrict__ sr, const float* __restrict__ si,
                     bf16* __restrict__ osr, bf16* __restrict__ osi, long long plane)
{
    const long long row = blockIdx.x;
    const float* pr = sr + row * (long long)SEQ;
    const float* pi = si + row * (long long)SEQ;
    const int t = threadIdx.x;
    const int i0 = t * 8;

    float vr[8], vi[8], mag[8], e[8];
    *(float4*)&vr[0] = *(const float4*)(pr + i0);
    *(float4*)&vr[4] = *(const float4*)(pr + i0 + 4);
    *(float4*)&vi[0] = *(const float4*)(pi + i0);
    *(float4*)&vi[4] = *(const float4*)(pi + i0 + 4);

    float mx = -1e30f;
#pragma unroll
    for (int i = 0; i < 8; i++) {
        mag[i] = sqrtf(vr[i] * vr[i] + vi[i] * vi[i]);
        mx = fmaxf(mx, mag[i]);
    }
    __shared__ float red[256];
    red[t] = mx; __syncthreads();
#pragma unroll
    for (int s = 128; s > 0; s >>= 1) {
        if (t < s) red[t] = fmaxf(red[t], red[t + s]);
        __syncthreads();
    }
    mx = red[0];
    __syncthreads();
    float sum = 0.f;
#pragma unroll
    for (int i = 0; i < 8; i++) { e[i] = expf(mag[i] - mx); sum += e[i]; }
    red[t] = sum; __syncthreads();
#pragma unroll
    for (int s = 128; s > 0; s >>= 1) {
        if (t < s) red[t] += red[t + s];
        __syncthreads();
    }
    sum = red[0];
    const float inv_s = 1.0f / (sum + 1e-8f);

    float orv[8], oiv[8];
#pragma unroll
    for (int i = 0; i < 8; i++) {
        float f = e[i] * inv_s / (mag[i] + 1e-8f);
        orv[i] = vr[i] * f; oiv[i] = vi[i] * f;
    }
    long long off = row * (long long)SEQ + i0;
    uint4 h, l;
    float r0, r1;
    h.x = pack_hi2(orv[0], orv[1], r0, r1); l.x = pack2(r0, r1);
    h.y = pack_hi2(orv[2], orv[3], r0, r1); l.y = pack2(r0, r1);
    h.z = pack_hi2(orv[4], orv[5], r0, r1); l.z = pack2(r0, r1);
    h.w = pack_hi2(orv[6], orv[7], r0, r1); l.w = pack2(r0, r1);
    *(uint4*)(osr + off) = h;
    *(uint4*)(osr + plane + off) = l;
    h.x = pack_hi2(oiv[0], oiv[1], r0, r1); l.x = pack2(r0, r1);
    h.y = pack_hi2(oiv[2], oiv[3], r0, r1); l.y = pack2(r0, r1);
    h.z = pack_hi2(oiv[4], oiv[5], r0, r1); l.z = pack2(r0, r1);
    h.w = pack_hi2(oiv[6], oiv[7], r0, r1); l.w = pack2(r0, r1);
    *(uint4*)(osi + off) = h;
    *(uint4*)(osi + plane + off) = l;
}

// Mf = 0.9*I + 0.1*flow_W  -> bf16 hi/lo planes directly
__global__ void build_mflow_kernel(const float* __restrict__ fw, bf16* __restrict__ mf,
                                   long long plane)
{
    int i = blockIdx.y * blockDim.y + threadIdx.y;
    int j = blockIdx.x * blockDim.x + threadIdx.x;
    float v = 0.1f * fw[(long long)i * MAN + j];
    if (i == j) v += 0.9f;
    bf16 h = __float2bfloat16(v);
    mf[(long long)i * MAN + j] = h;
    mf[plane + (long long)i * MAN + j] = __float2bfloat16(v - __bfloat162float(h));
}

// ---------------------------------------------------------------------------
// host-side
// ---------------------------------------------------------------------------
static void conv(const float* s, bf16* d, long long n)
{
    long long n4 = n / 4;
    convert_hilo_kernel<<<(unsigned)((n4 + 255) / 256), 256>>>(s, d, n4, n);
}
static void hgemm_b16(bool transb, const bf16* A, long long pA, const bf16* B, long long pB,
                      bf16* C, long long pC, const float* bias, int M, int N, int K)
{
    dim3 grid(N / 128, M / 128, 1);
    if (transb) hgemm_kernel<true, true><<<grid, 256>>>(A, B, nullptr, C, pC, bias, M, N, K, pA, pB, 1.f);
    else        hgemm_kernel<false, true><<<grid, 256>>>(A, B, nullptr, C, pC, bias, M, N, K, pA, pB, 1.f);
}
static void hgemm_f32_nn(const bf16* A, long long pA, const bf16* B, long long pB,
                         float* C, const float* bias, int M, int N, int K)
{
    dim3 grid(N / 128, M / 128, 1);
    hgemm_kernel<false, false><<<grid, 256>>>(A, B, C, nullptr, 0, bias, M, N, K, pA, pB, 1.f);
}

#define SMEM_NT (2 * (4 * APL + 4 * BPL_NT))
#define SMEM_NN (2 * (4 * APL + 4 * BPL_NN))

extern "C" void kernel_launch(void* const* d_in, const int* in_sizes, int n_in,
                              void* d_out, int out_size)
{
    const float* x      = (const float*)d_in[0];
    const float* Wp     = (const float*)d_in[1];
    const float* bp     = (const float*)d_in[2];
    const float* Wpinv  = (const float*)d_in[3];
    const float* bpinv  = (const float*)d_in[4];
    const float* aWr    = (const float*)d_in[5];
    const float* aWi    = (const float*)d_in[6];
    const float* abr    = (const float*)d_in[7];
    const float* abi    = (const float*)d_in[8];
    const float* metric = (const float*)d_in[9];
    const float* flowW  = (const float*)d_in[10];
    float* out = (float*)d_out;

    float *sr, *si;
    cudaGetSymbolAddress((void**)&sr, g_sr);
    cudaGetSymbolAddress((void**)&si, g_si);

    bf16 *cx, *cwp, *cwpinv, *cwr, *cwi, *cmet, *cm0, *cm1, *cm2, *ccpost;
    bf16 *cq0r, *cq0i, *cq1r, *cq1i, *car, *cai, *csr, *csi;
    cudaGetSymbolAddress((void**)&cx,     c_x);
    cudaGetSymbolAddress((void**)&cwp,    c_wp);
    cudaGetSymbolAddress((void**)&cwpinv, c_wpinv);
    cudaGetSymbolAddress((void**)&cwr,    c_wr);
    cudaGetSymbolAddress((void**)&cwi,    c_wi);
    cudaGetSymbolAddress((void**)&cmet,   c_met);
    cudaGetSymbolAddress((void**)&cm0,    c_m0);
    cudaGetSymbolAddress((void**)&cm1,    c_m1);
    cudaGetSymbolAddress((void**)&cm2,    c_m2);
    cudaGetSymbolAddress((void**)&ccpost, c_cpost);
    cudaGetSymbolAddress((void**)&cq0r,   c_q0r);
    cudaGetSymbolAddress((void**)&cq0i,   c_q0i);
    cudaGetSymbolAddress((void**)&cq1r,   c_q1r);
    cudaGetSymbolAddress((void**)&cq1i,   c_q1i);
    cudaGetSymbolAddress((void**)&car,    c_ar);
    cudaGetSymbolAddress((void**)&cai,    c_ai);
    cudaGetSymbolAddress((void**)&csr,    c_sr);
    cudaGetSymbolAddress((void**)&csi,    c_si);

    cudaFuncSetAttribute(cgemm_kernel<true, false, false, true, true, false, true, false>,
                         cudaFuncAttributeMaxDynamicSharedMemorySize, SMEM_NT);
    cudaFuncSetAttribute(cgemm_kernel<true, false, true, true, true, false, true, false>,
                         cudaFuncAttributeMaxDynamicSharedMemorySize, SMEM_NT);
    cudaFuncSetAttribute(cgemm_kernel<true, true, true, true, true, true, false, true>,
                         cudaFuncAttributeMaxDynamicSharedMemorySize, SMEM_NT);
    cudaFuncSetAttribute(cgemm_kernel<false, false, true, false, true, false, true, false>,
                         cudaFuncAttributeMaxDynamicSharedMemorySize, SMEM_NN);
    cudaFuncSetAttribute(cgemm_kernel<false, false, true, true, true, false, true, false>,
                         cudaFuncAttributeMaxDynamicSharedMemorySize, SMEM_NN);
    cudaFuncSetAttribute(cgemm_kernel<false, false, true, true, false, false, true, false>,
                         cudaFuncAttributeMaxDynamicSharedMemorySize, SMEM_NN);

    const float scale = 0.03125f;                 // 1/sqrt(1024)
    const long long sQ = (long long)SEQ * MAN;
    const long long sS = (long long)SEQ * SEQ;
    const long long pMM = (long long)MAN * MAN;
    const long long pQ  = (long long)ROWS * MAN;
    const long long pS  = (long long)BATCH * SEQ * SEQ;

    conv(x, cx, (long long)ROWS * HID);
    conv(Wp, cwp, (long long)MAN * HID);
    conv(aWr, cwr, pMM);
    conv(aWi, cwi, pMM);

    hgemm_b16(true, cx, (long long)ROWS * HID, cwp, (long long)MAN * HID,
              cq0r, pQ, bp, ROWS, MAN, HID);

    bf16 *cqr = cq0r, *cqi = cq0i, *cqnr = cq1r, *cqni = cq1i;

    for (int l = 0; l < NLAYERS; l++) {
        if (l > 0) {
            conv(aWr + (long long)l * pMM, cwr + (long long)l * 2 * pMM, pMM);
            conv(aWi + (long long)l * pMM, cwi + (long long)l * 2 * pMM, pMM);
        }
        const bf16* Wr = cwr + (long long)l * 2 * pMM;
        const bf16* Wi = cwi + (long long)l * 2 * pMM;
        const float* br = abr + (long long)l * MAN;
        const float* bi = abi + (long long)l * MAN;

        // a = q (*) W^T + b
        {
            dim3 grid(MAN / 128, ROWS / 128, 1);
            if (l == 0)
                cgemm_kernel<true, false, false, true, true, false, true, false><<<grid, 256, SMEM_NT>>>(
                    cqr, cqi, pQ, Wr, Wi, pMM,
                    nullptr, nullptr, car, cai, pQ, br, bi,
                    ROWS, MAN, MAN, 0, 0, 0, 1.f);
            else
                cgemm_kernel<true, false, true, true, true, false, true, false><<<grid, 256, SMEM_NT>>>(
                    cqr, cqi, pQ, Wr, Wi, pMM,
                    nullptr, nullptr, car, cai, pQ, br, bi,
                    ROWS, MAN, MAN, 0, 0, 0, 1.f);
        }

        // scores = scale * a (*) conj(a)^T  (Hermitian; fp32 + SMEM-T mirror)
        {
            dim3 grid(136, 1, BATCH);
            cgemm_kernel<true, true, true, true, true, true, false, true><<<grid, 256, SMEM_NT>>>(
                car, cai, pQ, car, cai, pQ,
                sr, si, nullptr, nullptr, pS, nullptr, nullptr,
                SEQ, SEQ, MAN, sQ, sQ, sS, scale);
        }

        csoftmax_kernel<<<BATCH * SEQ, 256>>>(sr, si, csr, csi, pS);

        // q' = attn (*) q
        {
            dim3 grid(MAN / 128, SEQ / 128, BATCH);
            if (l == 0)
                cgemm_kernel<false, false, true, false, true, false, true, false><<<grid, 256, SMEM_NN>>>(
                    csr, csi, pS, cqr, cqi, pQ,
                    nullptr, nullptr, cqnr, cqni, pQ, nullptr, nullptr,
                    SEQ, MAN, SEQ, sS, sQ, sQ, 1.f);
            else if (l < NLAYERS - 1)
                cgemm_kernel<false, false, true, true, true, false, true, false><<<grid, 256, SMEM_NN>>>(
                    csr, csi, pS, cqr, cqi, pQ,
                    nullptr, nullptr, cqnr, cqni, pQ, nullptr, nullptr,
                    SEQ, MAN, SEQ, sS, sQ, sQ, 1.f);
            else
                cgemm_kernel<false, false, true, true, false, false, true, false><<<grid, 256, SMEM_NN>>>(
                    csr, csi, pS, cqr, cqi, pQ,
                    nullptr, nullptr, cqnr, cqni, pQ, nullptr, nullptr,
                    SEQ, MAN, SEQ, sS, sQ, sQ, 1.f);
        }

        bf16* tr = cqr; cqr = cqnr; cqnr = tr;
        bf16* ti = cqi; cqi = cqni; cqni = ti;
    }

    // ---- setup chain (convert-free): cpost = metric * Mf^10 * Wpinv^T ----
    conv(metric, cmet, pMM);
    conv(Wpinv, cwpinv, (long long)HID * MAN);
    {
        dim3 blk(16, 16), grd(MAN / 16, MAN / 16);
        build_mflow_kernel<<<grd, blk>>>(flowW, cm0, pMM);
    }
    hgemm_b16(false, cm0, pMM, cm0, pMM, cm1, pMM, nullptr, MAN, MAN, MAN);   // Mf^2
    hgemm_b16(false, cm1, pMM, cm1, pMM, cm2, pMM, nullptr, MAN, MAN, MAN);   // Mf^4
    hgemm_b16(false, cm2, pMM, cm2, pMM, cm0, pMM, nullptr, MAN, MAN, MAN);   // Mf^8
    hgemm_b16(false, cm0, pMM, cm1, pMM, cm2, pMM, nullptr, MAN, MAN, MAN);   // Mf^10
    hgemm_b16(false, cmet, pMM, cm2, pMM, cm1, pMM, nullptr, MAN, MAN, MAN);  // g*Mf^10
    hgemm_b16(true, cm1, pMM, cwpinv, (long long)HID * MAN, ccpost,
              (long long)MAN * HID, nullptr, MAN, HID, MAN);                  // * Wpinv^T

    // ---- out = Re(q) @ Cpost + bp_inv ----
    hgemm_f32_nn(cqr, pQ, ccpost, (long long)MAN * HID, out, bpinv, ROWS, HID, MAN);
}

// round 11
// speedup vs baseline: 1.1865x; 1.0442x over previous
#include <cuda_runtime.h>
#include <cuda_bf16.h>
#include <stdint.h>
#include <math.h>

// ---------------------------------------------------------------------------
// QuantumGeometricAttention forward.  Fused complex HMMA GEMMs, bf16 hi/lo
// split (3 passes per real product), cp.async double buffering (BK=32),
// Hermitian scores (triangular + scatter mirror).  Setup-chain GEMMs use
// BM=64 tiles (128 CTAs) to cut serial small-GEMM tail.
// ---------------------------------------------------------------------------

#define BATCH 2
#define SEQ   2048
#define HID   1024
#define MAN   1024
#define ROWS  (BATCH * SEQ)
#define NLAYERS 3

typedef __nv_bfloat16 bf16;

// ---------------- fp32 scratch ----------------------------------------------
__device__ float g_sr [(size_t)BATCH * SEQ * SEQ];
__device__ float g_si [(size_t)BATCH * SEQ * SEQ];

// ---------------- bf16 hi/lo planes (hi at 0, lo at +plane) ------------------
__device__ bf16 c_x    [2 * (size_t)ROWS * HID];
__device__ bf16 c_wp   [2 * (size_t)MAN * HID];
__device__ bf16 c_wpinv[2 * (size_t)HID * MAN];
__device__ bf16 c_wr   [(size_t)NLAYERS * 2 * MAN * MAN];
__device__ bf16 c_wi   [(size_t)NLAYERS * 2 * MAN * MAN];
__device__ bf16 c_met  [2 * (size_t)MAN * MAN];
__device__ bf16 c_m0   [2 * (size_t)MAN * MAN];
__device__ bf16 c_m1   [2 * (size_t)MAN * MAN];
__device__ bf16 c_m2   [2 * (size_t)MAN * MAN];
__device__ bf16 c_cpost[2 * (size_t)MAN * HID];
__device__ bf16 c_q0r  [2 * (size_t)ROWS * MAN];
__device__ bf16 c_q0i  [2 * (size_t)ROWS * MAN];
__device__ bf16 c_q1r  [2 * (size_t)ROWS * MAN];
__device__ bf16 c_q1i  [2 * (size_t)ROWS * MAN];
__device__ bf16 c_ar   [2 * (size_t)ROWS * MAN];
__device__ bf16 c_ai   [2 * (size_t)ROWS * MAN];
__device__ bf16 c_sr   [2 * (size_t)BATCH * SEQ * SEQ];
__device__ bf16 c_si   [2 * (size_t)BATCH * SEQ * SEQ];

// ---------------------------- helpers ---------------------------------------
__device__ __forceinline__ uint32_t smem_u32(const void* p) {
    uint32_t a;
    asm("{ .reg .u64 t; cvta.to.shared.u64 t, %1; cvt.u32.u64 %0, t; }" : "=r"(a) : "l"(p));
    return a;
}
__device__ __forceinline__ void cp16(uint32_t dst, const void* src) {
    asm volatile("{ .reg .u64 g; cvta.to.global.u64 g, %1; cp.async.cg.shared.global [%0], [g], 16; }"
                 :: "r"(dst), "l"(src) : "memory");
}
#define CP_COMMIT() asm volatile("cp.async.commit_group;" ::: "memory")
#define CP_WAIT(n)  asm volatile("cp.async.wait_group %0;" :: "n"(n) : "memory")

#define MMA(d, a, b0, b1) \
    asm volatile("mma.sync.aligned.m16n8k16.row.col.f32.bf16.bf16.f32 " \
        "{%0,%1,%2,%3}, {%4,%5,%6,%7}, {%8,%9}, {%0,%1,%2,%3};" \
        : "+f"((d)[0]), "+f"((d)[1]), "+f"((d)[2]), "+f"((d)[3]) \
        : "r"((a)[0]), "r"((a)[1]), "r"((a)[2]), "r"((a)[3]), "r"(b0), "r"(b1))

__device__ __forceinline__ uint32_t pack_hi2(float a, float b, float& ra, float& rb) {
    bf16 h0 = __float2bfloat16(a), h1 = __float2bfloat16(b);
    ra = a - __bfloat162float(h0); rb = b - __bfloat162float(h1);
    return (uint32_t)__bfloat16_as_ushort(h0) | ((uint32_t)__bfloat16_as_ushort(h1) << 16);
}
__device__ __forceinline__ uint32_t pack2(float a, float b) {
    return (uint32_t)__bfloat16_as_ushort(__float2bfloat16(a)) |
           ((uint32_t)__bfloat16_as_ushort(__float2bfloat16(b)) << 16);
}

// ---------------------------------------------------------------------------
// fp32 -> bf16 hi/lo convert
// ---------------------------------------------------------------------------
__global__ __launch_bounds__(256)
void convert_hilo_kernel(const float* __restrict__ src, bf16* __restrict__ dst,
                         long long n4, long long plane)
{
    long long i = (long long)blockIdx.x * blockDim.x + threadIdx.x;
    if (i >= n4) return;
    float4 v = ((const float4*)src)[i];
    float r0, r1, r2, r3;
    uint2 hp, lp;
    hp.x = pack_hi2(v.x, v.y, r0, r1);
    hp.y = pack_hi2(v.z, v.w, r2, r3);
    lp.x = pack2(r0, r1);
    lp.y = pack2(r2, r3);
    ((uint2*)dst)[i] = hp;
    ((uint2*)(dst + plane))[i] = lp;
}

// ---------------------------------------------------------------------------
// Real HMMA GEMM (BK=32), bf16 hi/lo 3-pass; templated tile height BM.
// ---------------------------------------------------------------------------
template<bool TRANSB, bool WB16, int BM>
__global__ __launch_bounds__(256, 2)
void hgemm_kernel(const bf16* __restrict__ A, const bf16* __restrict__ B,
                  float* __restrict__ Cf, bf16* __restrict__ Cb, long long planeC,
                  const float* __restrict__ bias,
                  int M, int N, int K,
                  long long planeA, long long planeB,
                  float alpha)
{
    constexpr int MI = BM / 32;             // warp m-subtiles of 16 rows
    __shared__ __align__(16) bf16 sAm[2][BM][40];
    __shared__ __align__(16) bf16 sBm[2][5120];

    const int bm = blockIdx.y * BM;
    const int bn = blockIdx.x * 128;
    const int t = threadIdx.x, wid = t >> 5, lane = t & 31;
    const int wm = (wid >> 2) * (MI * 16), wn = (wid & 3) * 32;

    float acc[MI][4][4];
#pragma unroll
    for (int a = 0; a < MI; a++)
#pragma unroll
        for (int b = 0; b < 4; b++)
#pragma unroll
            for (int c = 0; c < 4; c++) acc[a][b][c] = 0.f;

    for (int k0 = 0; k0 < K; k0 += 32) {
        __syncthreads();
#pragma unroll
        for (int p = 0; p < 2; p++)
#pragma unroll
            for (int i = 0; i < BM / 64; i++) {
                int u = t + (i << 8);
                int r = u >> 2, kq = (u & 3) << 3;
                *(uint4*)&sAm[p][r][kq] =
                    *(const uint4*)(A + (long long)p * planeA + (long long)(bm + r) * K + k0 + kq);
            }
        if (TRANSB) {
#pragma unroll
            for (int p = 0; p < 2; p++)
#pragma unroll
                for (int i = 0; i < 2; i++) {
                    int u = t + (i << 8);
                    int r = u >> 2, kq = (u & 3) << 3;
                    *(uint4*)&sBm[p][r * 40 + kq] =
                        *(const uint4*)(B + (long long)p * planeB + (long long)(bn + r) * K + k0 + kq);
                }
        } else {
#pragma unroll
            for (int p = 0; p < 2; p++)
#pragma unroll
                for (int i = 0; i < 2; i++) {
                    int u = t + (i << 8);
                    int kr = u >> 4, nq = (u & 15) << 3;
                    *(uint4*)&sBm[p][kr * 136 + nq] =
                        *(const uint4*)(B + (long long)p * planeB + (long long)(k0 + kr) * N + bn + nq);
                }
        }
        __syncthreads();

#pragma unroll
        for (int kk = 0; kk < 2; kk++) {
            uint32_t Af[MI][4];
            uint32_t Bf[8];
            auto loadB = [&](int p) {
                if (TRANSB) {
                    uint32_t a0 = smem_u32(&sBm[p][(wn + ((lane >> 4) << 3) + (lane & 7)) * 40 + kk * 16 + (lane & 8)]);
                    asm volatile("ldmatrix.sync.aligned.m8n8.x4.shared.b16 {%0,%1,%2,%3}, [%4];"
                        : "=r"(Bf[0]), "=r"(Bf[1]), "=r"(Bf[2]), "=r"(Bf[3]) : "r"(a0));
                    uint32_t a1 = smem_u32(&sBm[p][(wn + 16 + ((lane >> 4) << 3) + (lane & 7)) * 40 + kk * 16 + (lane & 8)]);
                    asm volatile("ldmatrix.sync.aligned.m8n8.x4.shared.b16 {%0,%1,%2,%3}, [%4];"
                        : "=r"(Bf[4]), "=r"(Bf[5]), "=r"(Bf[6]), "=r"(Bf[7]) : "r"(a1));
                } else {
                    uint32_t a0 = smem_u32(&sBm[p][(kk * 16 + (lane & 7) + (lane & 8)) * 136 + wn + ((lane >> 4) << 3)]);
                    asm volatile("ldmatrix.sync.aligned.m8n8.x4.trans.shared.b16 {%0,%1,%2,%3}, [%4];"
                        : "=r"(Bf[0]), "=r"(Bf[1]), "=r"(Bf[2]), "=r"(Bf[3]) : "r"(a0));
                    uint32_t a1 = smem_u32(&sBm[p][(kk * 16 + (lane & 7) + (lane & 8)) * 136 + wn + 16 + ((lane >> 4) << 3)]);
                    asm volatile("ldmatrix.sync.aligned.m8n8.x4.trans.shared.b16 {%0,%1,%2,%3}, [%4];"
                        : "=r"(Bf[4]), "=r"(Bf[5]), "=r"(Bf[6]), "=r"(Bf[7]) : "r"(a1));
                }
            };
            auto loadA = [&](int p) {
#pragma unroll
                for (int mi = 0; mi < MI; mi++) {
                    uint32_t ad = smem_u32(&sAm[p][wm + mi * 16 + (lane & 15)][kk * 16 + ((lane >> 4) << 3)]);
                    asm volatile("ldmatrix.sync.aligned.m8n8.x4.shared.b16 {%0,%1,%2,%3}, [%4];"
                        : "=r"(Af[mi][0]), "=r"(Af[mi][1]), "=r"(Af[mi][2]), "=r"(Af[mi][3]) : "r"(ad));
                }
            };
            auto mmAll = [&]() {
#pragma unroll
                for (int mi = 0; mi < MI; mi++)
#pragma unroll
                    for (int nj = 0; nj < 4; nj++)
                        MMA(acc[mi][nj], Af[mi], Bf[2 * nj], Bf[2 * nj + 1]);
            };
            loadA(0); loadB(0); mmAll();
            loadB(1);           mmAll();
            loadA(1); loadB(0); mmAll();
        }
    }

#pragma unroll
    for (int mi = 0; mi < MI; mi++)
#pragma unroll
        for (int nj = 0; nj < 4; nj++) {
            int r0 = bm + wm + mi * 16 + (lane >> 2);
            int cc = bn + wn + nj * 8 + ((lane & 3) << 1);
            float2 bb = make_float2(0.f, 0.f);
            if (bias) bb = *(const float2*)(bias + cc);
#pragma unroll
            for (int h = 0; h < 2; h++) {
                long long off = (long long)(r0 + h * 8) * N + cc;
                float v0 = alpha * acc[mi][nj][2 * h + 0] + bb.x;
                float v1 = alpha * acc[mi][nj][2 * h + 1] + bb.y;
                if (WB16) {
                    float l0, l1;
                    *(uint32_t*)(Cb + off) = pack_hi2(v0, v1, l0, l1);
                    *(uint32_t*)(Cb + planeC + off) = pack2(l0, l1);
                } else {
                    *(float2*)(Cf + off) = make_float2(v0, v1);
                }
            }
        }
}

// ---------------------------------------------------------------------------
// Fused complex HMMA GEMM (BK=32, 12 passes for full complex).
//   HERM: lower-triangular tiles + scatter conjugate mirror (champion R5).
// ---------------------------------------------------------------------------
#define APL 10240
#define BPL_NT 10240
#define BPL_NN 8704

template<bool TRANSB, bool CONJ, bool HAS_AI, bool HAS_BI, bool WANT_I,
         bool WF32, bool WB16, bool HERM>
__global__ __launch_bounds__(256, 1)
void cgemm_kernel(const bf16* __restrict__ Ar, const bf16* __restrict__ Ai, long long planeA,
                  const bf16* __restrict__ Br, const bf16* __restrict__ Bi, long long planeB,
                  float* __restrict__ CrF, float* __restrict__ CiF,
                  bf16* __restrict__ CrB, bf16* __restrict__ CiB, long long planeC,
                  const float* __restrict__ biasR, const float* __restrict__ biasI,
                  int M, int N, int K,
                  long long sA, long long sB, long long sC,
                  float alpha)
{
    extern __shared__ __align__(16) char smem[];
    constexpr int BPL = TRANSB ? BPL_NT : BPL_NN;
    constexpr int ASZ = 4 * APL;
    constexpr int STG = ASZ + 4 * BPL;

    const long long zb = blockIdx.z;
    Ar += zb * sA; if (HAS_AI) Ai += zb * sA;
    Br += zb * sB; if (HAS_BI) Bi += zb * sB;

    int bi, bj;
    if (HERM) {
        int bx = blockIdx.x;
        bi = (int)((sqrtf(8.f * bx + 1.f) - 1.f) * 0.5f);
        while ((bi + 1) * (bi + 2) / 2 <= bx) bi++;
        while (bi * (bi + 1) / 2 > bx) bi--;
        bj = bx - bi * (bi + 1) / 2;
    } else {
        bi = blockIdx.y; bj = blockIdx.x;
    }
    const int bm = bi * 128;
    const int bn = bj * 128;
    const int t = threadIdx.x, wid = t >> 5, lane = t & 31;
    const int wm = (wid >> 2) * 64, wn = (wid & 3) * 32;

    const uint32_t sbase = smem_u32(smem);
    const bf16* aps[4] = { Ar, Ar + planeA, Ai, HAS_AI ? (Ai + planeA) : Ai };
    const bf16* bps[4] = { Br, Br + planeB, Bi, HAS_BI ? (Bi + planeB) : Bi };
    const int NPA = HAS_AI ? 4 : 2;
    const int NPB = HAS_BI ? 4 : 2;

    auto issue = [&](int c, int buf) {
        const int k0 = c << 5;
        const uint32_t stg = sbase + (uint32_t)buf * STG;
        for (int p = 0; p < NPA; p++) {
#pragma unroll
            for (int i = 0; i < 2; i++) {
                int u = t + (i << 8);
                int r = u >> 2, cq = (u & 3) << 3;
                cp16(stg + p * APL + (r * 40 + cq) * 2,
                     aps[p] + (long long)(bm + r) * K + k0 + cq);
            }
        }
        if (TRANSB) {
            for (int p = 0; p < NPB; p++) {
#pragma unroll
                for (int i = 0; i < 2; i++) {
                    int u = t + (i << 8);
                    int r = u >> 2, cq = (u & 3) << 3;
                    cp16(stg + ASZ + p * BPL + (r * 40 + cq) * 2,
                         bps[p] + (long long)(bn + r) * K + k0 + cq);
                }
            }
        } else {
            for (int p = 0; p < NPB; p++) {
#pragma unroll
                for (int i = 0; i < 2; i++) {
                    int u = t + (i << 8);
                    int kr = u >> 4, nq = (u & 15) << 3;
                    cp16(stg + ASZ + p * BPL + (kr * 136 + nq) * 2,
                         bps[p] + (long long)(k0 + kr) * N + bn + nq);
                }
            }
        }
        CP_COMMIT();
    };

    float accR[4][4][4], accI[4][4][4];
#pragma unroll
    for (int a = 0; a < 4; a++)
#pragma unroll
        for (int b = 0; b < 4; b++)
#pragma unroll
            for (int c = 0; c < 4; c++) { accR[a][b][c] = 0.f; accI[a][b][c] = 0.f; }

    const int nch = K >> 5;
    issue(0, 0);

    for (int c = 0; c < nch; c++) {
        const int buf = c & 1;
        if (c + 1 < nch) { issue(c + 1, buf ^ 1); CP_WAIT(1); }
        else             { CP_WAIT(0); }
        __syncthreads();

        bf16* sAp = (bf16*)(smem + buf * STG);
        bf16* sBp = (bf16*)(smem + buf * STG + ASZ);

#pragma unroll
        for (int kk = 0; kk < 2; kk++) {
            uint32_t brh[8], brl[8], bih[8], bil[8];
            auto loadB = [&](int p, uint32_t* o) {
                bf16* bp = (bf16*)((char*)sBp + p * BPL);
                if (TRANSB) {
                    uint32_t a0 = smem_u32(&bp[(wn + ((lane >> 4) << 3) + (lane & 7)) * 40 + kk * 16 + (lane & 8)]);
                    asm volatile("ldmatrix.sync.aligned.m8n8.x4.shared.b16 {%0,%1,%2,%3}, [%4];"
                        : "=r"(o[0]), "=r"(o[1]), "=r"(o[2]), "=r"(o[3]) : "r"(a0));
                    uint32_t a1 = smem_u32(&bp[(wn + 16 + ((lane >> 4) << 3) + (lane & 7)) * 40 + kk * 16 + (lane & 8)]);
                    asm volatile("ldmatrix.sync.aligned.m8n8.x4.shared.b16 {%0,%1,%2,%3}, [%4];"
                        : "=r"(o[4]), "=r"(o[5]), "=r"(o[6]), "=r"(o[7]) : "r"(a1));
                } else {
                    uint32_t a0 = smem_u32(&bp[(kk * 16 + (lane & 7) + (lane & 8)) * 136 + wn + ((lane >> 4) << 3)]);
                    asm volatile("ldmatrix.sync.aligned.m8n8.x4.trans.shared.b16 {%0,%1,%2,%3}, [%4];"
                        : "=r"(o[0]), "=r"(o[1]), "=r"(o[2]), "=r"(o[3]) : "r"(a0));
                    uint32_t a1 = smem_u32(&bp[(kk * 16 + (lane & 7) + (lane & 8)) * 136 + wn + 16 + ((lane >> 4) << 3)]);
                    asm volatile("ldmatrix.sync.aligned.m8n8.x4.trans.shared.b16 {%0,%1,%2,%3}, [%4];"
                        : "=r"(o[4]), "=r"(o[5]), "=r"(o[6]), "=r"(o[7]) : "r"(a1));
                }
            };
            loadB(0, brh); loadB(1, brl);
            if (HAS_BI) { loadB(2, bih); loadB(3, bil); }

            uint32_t Af[4][4];
            auto loadA = [&](int p) {
                bf16* ap = (bf16*)((char*)sAp + p * APL);
#pragma unroll
                for (int mi = 0; mi < 4; mi++) {
                    uint32_t ad = smem_u32(&ap[(wm + mi * 16 + (lane & 15)) * 40 + kk * 16 + ((lane >> 4) << 3)]);
                    asm volatile("ldmatrix.sync.aligned.m8n8.x4.shared.b16 {%0,%1,%2,%3}, [%4];"
                        : "=r"(Af[mi][0]), "=r"(Af[mi][1]), "=r"(Af[mi][2]), "=r"(Af[mi][3]) : "r"(ad));
                }
            };
            auto negA = [&]() {
#pragma unroll
                for (int mi = 0; mi < 4; mi++)
#pragma unroll
                    for (int j = 0; j < 4; j++) Af[mi][j] ^= 0x80008000u;
            };
            auto mmP = [&](float (*acc)[4][4], const uint32_t* b) {
#pragma unroll
                for (int mi = 0; mi < 4; mi++)
#pragma unroll
                    for (int nj = 0; nj < 4; nj++)
                        MMA(acc[mi][nj], Af[mi], b[2 * nj], b[2 * nj + 1]);
            };

            loadA(0);
            mmP(accR, brh); mmP(accR, brl);
            if (WANT_I && HAS_BI) {
                if (CONJ) negA();
                mmP(accI, bih); mmP(accI, bil);
            }
            loadA(1);
            mmP(accR, brh);
            if (WANT_I && HAS_BI) { if (CONJ) negA(); mmP(accI, bih); }
            if (HAS_AI) {
                loadA(2);
                if (WANT_I) { mmP(accI, brh); mmP(accI, brl); }
                if (HAS_BI) {
                    if (!CONJ) negA();
                    mmP(accR, bih); mmP(accR, bil);
                }
                loadA(3);
                if (WANT_I) mmP(accI, brh);
                if (HAS_BI) { if (!CONJ) negA(); mmP(accR, bih); }
            }
        }
        __syncthreads();
    }

    // ---- epilogue (scatter mirror, champion R5) ----
    float* crf = WF32 ? CrF + zb * sC : nullptr;
    float* cif = (WF32 && WANT_I) ? CiF + zb * sC : nullptr;
    bf16*  crb = WB16 ? CrB + zb * sC : nullptr;
    bf16*  cib = (WB16 && WANT_I) ? CiB + zb * sC : nullptr;
    const bool mirror = HERM && (bi != bj);

#pragma unroll
    for (int mi = 0; mi < 4; mi++)
#pragma unroll
        for (int nj = 0; nj < 4; nj++) {
            int r0 = bm + wm + mi * 16 + (lane >> 2);
            int cc = bn + wn + nj * 8 + ((lane & 3) << 1);
            float bR0 = 0.f, bR1 = 0.f, bI0 = 0.f, bI1 = 0.f;
            if (biasR) { bR0 = biasR[cc]; bR1 = biasR[cc + 1]; }
            if (WANT_I && biasI) { bI0 = biasI[cc]; bI1 = biasI[cc + 1]; }
#pragma unroll
            for (int h = 0; h < 2; h++) {
                long long row = r0 + h * 8;
                long long off = row * N + cc;
                float vr0 = alpha * accR[mi][nj][2 * h + 0] + bR0;
                float vr1 = alpha * accR[mi][nj][2 * h + 1] + bR1;
                float vi0 = 0.f, vi1 = 0.f;
                if (WANT_I) {
                    vi0 = alpha * accI[mi][nj][2 * h + 0] + bI0;
                    vi1 = alpha * accI[mi][nj][2 * h + 1] + bI1;
                }
                if (WF32) {
                    *(float2*)(crf + off) = make_float2(vr0, vr1);
                    if (WANT_I) *(float2*)(cif + off) = make_float2(vi0, vi1);
                    if (mirror) {
                        crf[(long long)cc * N + row] = vr0;
                        crf[(long long)(cc + 1) * N + row] = vr1;
                        if (WANT_I) {
                            cif[(long long)cc * N + row] = -vi0;
                            cif[(long long)(cc + 1) * N + row] = -vi1;
                        }
                    }
                }
                if (WB16) {
                    float l0, l1;
                    *(uint32_t*)(crb + off) = pack_hi2(vr0, vr1, l0, l1);
                    *(uint32_t*)(crb + planeC + off) = pack2(l0, l1);
                    if (WANT_I) {
                        *(uint32_t*)(cib + off) = pack_hi2(vi0, vi1, l0, l1);
                        *(uint32_t*)(cib + planeC + off) = pack2(l0, l1);
                    }
                }
            }
        }
}

// ---------------------------------------------------------------------------
// Complex softmax: fp32 (sr,si) in, bf16 hi/lo planes out.
// ---------------------------------------------------------------------------
__global__ __launch_bounds__(256)
void csoftmax_kernel(const float* __restrict__ sr, const float* __restrict__ si,
                     bf16* __restrict__ osr, bf16* __restrict__ osi, long long plane)
{
    const long long row = blockIdx.x;
    const float* pr = sr + row * (long long)SEQ;
    const float* pi = si + row * (long long)SEQ;
    const int t = threadIdx.x;
    const int i0 = t * 8;

    float vr[8], vi[8], mag[8], e[8];
    *(float4*)&vr[0] = *(const float4*)(pr + i0);
    *(float4*)&vr[4] = *(const float4*)(pr + i0 + 4);
    *(float4*)&vi[0] = *(const float4*)(pi + i0);
    *(float4*)&vi[4] = *(const float4*)(pi + i0 + 4);

    float mx = -1e30f;
#pragma unroll
    for (int i = 0; i < 8; i++) {
        mag[i] = sqrtf(vr[i] * vr[i] + vi[i] * vi[i]);
        mx = fmaxf(mx, mag[i]);
    }
    __shared__ float red[256];
    red[t] = mx; __syncthreads();
#pragma unroll
    for (int s = 128; s > 0; s >>= 1) {
        if (t < s) red[t] = fmaxf(red[t], red[t + s]);
        __syncthreads();
    }
    mx = red[0];
    __syncthreads();
    float sum = 0.f;
#pragma unroll
    for (int i = 0; i < 8; i++) { e[i] = expf(mag[i] - mx); sum += e[i]; }
    red[t] = sum; __syncthreads();
#pragma unroll
    for (int s = 128; s > 0; s >>= 1) {
        if (t < s) red[t] += red[t + s];
        __syncthreads();
    }
    sum = red[0];
    const float inv_s = 1.0f / (sum + 1e-8f);

    float orv[8], oiv[8];
#pragma unroll
    for (int i = 0; i < 8; i++) {
        float f = e[i] * inv_s / (mag[i] + 1e-8f);
        orv[i] = vr[i] * f; oiv[i] = vi[i] * f;
    }
    long long off = row * (long long)SEQ + i0;
    uint4 h, l;
    float r0, r1;
    h.x = pack_hi2(orv[0], orv[1], r0, r1); l.x = pack2(r0, r1);
    h.y = pack_hi2(orv[2], orv[3], r0, r1); l.y = pack2(r0, r1);
    h.z = pack_hi2(orv[4], orv[5], r0, r1); l.z = pack2(r0, r1);
    h.w = pack_hi2(orv[6], orv[7], r0, r1); l.w = pack2(r0, r1);
    *(uint4*)(osr + off) = h;
    *(uint4*)(osr + plane + off) = l;
    h.x = pack_hi2(oiv[0], oiv[1], r0, r1); l.x = pack2(r0, r1);
    h.y = pack_hi2(oiv[2], oiv[3], r0, r1); l.y = pack2(r0, r1);
    h.z = pack_hi2(oiv[4], oiv[5], r0, r1); l.z = pack2(r0, r1);
    h.w = pack_hi2(oiv[6], oiv[7], r0, r1); l.w = pack2(r0, r1);
    *(uint4*)(osi + off) = h;
    *(uint4*)(osi + plane + off) = l;
}

// Mf = 0.9*I + 0.1*flow_W  -> bf16 hi/lo planes directly
__global__ void build_mflow_kernel(const float* __restrict__ fw, bf16* __restrict__ mf,
                                   long long plane)
{
    int i = blockIdx.y * blockDim.y + threadIdx.y;
    int j = blockIdx.x * blockDim.x + threadIdx.x;
    float v = 0.1f * fw[(long long)i * MAN + j];
    if (i == j) v += 0.9f;
    bf16 h = __float2bfloat16(v);
    mf[(long long)i * MAN + j] = h;
    mf[plane + (long long)i * MAN + j] = __float2bfloat16(v - __bfloat162float(h));
}

// ---------------------------------------------------------------------------
// host-side
// ---------------------------------------------------------------------------
static void conv(const float* s, bf16* d, long long n)
{
    long long n4 = n / 4;
    convert_hilo_kernel<<<(unsigned)((n4 + 255) / 256), 256>>>(s, d, n4, n);
}
static void hgemm_b16_128(bool transb, const bf16* A, long long pA, const bf16* B, long long pB,
                          bf16* C, long long pC, const float* bias, int M, int N, int K)
{
    dim3 grid(N / 128, M / 128, 1);
    if (transb) hgemm_kernel<true, true, 128><<<grid, 256>>>(A, B, nullptr, C, pC, bias, M, N, K, pA, pB, 1.f);
    else        hgemm_kernel<false, true, 128><<<grid, 256>>>(A, B, nullptr, C, pC, bias, M, N, K, pA, pB, 1.f);
}
static void hgemm_b16_64(bool transb, const bf16* A, long long pA, const bf16* B, long long pB,
                         bf16* C, long long pC, int M, int N, int K)
{
    dim3 grid(N / 128, M / 64, 1);
    if (transb) hgemm_kernel<true, true, 64><<<grid, 256>>>(A, B, nullptr, C, pC, nullptr, M, N, K, pA, pB, 1.f);
    else        hgemm_kernel<false, true, 64><<<grid, 256>>>(A, B, nullptr, C, pC, nullptr, M, N, K, pA, pB, 1.f);
}
static void hgemm_f32_nn(const bf16* A, long long pA, const bf16* B, long long pB,
                         float* C, const float* bias, int M, int N, int K)
{
    dim3 grid(N / 128, M / 128, 1);
    hgemm_kernel<false, false, 128><<<grid, 256>>>(A, B, C, nullptr, 0, bias, M, N, K, pA, pB, 1.f);
}

#define SMEM_NT (2 * (4 * APL + 4 * BPL_NT))
#define SMEM_NN (2 * (4 * APL + 4 * BPL_NN))

extern "C" void kernel_launch(void* const* d_in, const int* in_sizes, int n_in,
                              void* d_out, int out_size)
{
    const float* x      = (const float*)d_in[0];
    const float* Wp     = (const float*)d_in[1];
    const float* bp     = (const float*)d_in[2];
    const float* Wpinv  = (const float*)d_in[3];
    const float* bpinv  = (const float*)d_in[4];
    const float* aWr    = (const float*)d_in[5];
    const float* aWi    = (const float*)d_in[6];
    const float* abr    = (const float*)d_in[7];
    const float* abi    = (const float*)d_in[8];
    const float* metric = (const float*)d_in[9];
    const float* flowW  = (const float*)d_in[10];
    float* out = (float*)d_out;

    float *sr, *si;
    cudaGetSymbolAddress((void**)&sr, g_sr);
    cudaGetSymbolAddress((void**)&si, g_si);

    bf16 *cx, *cwp, *cwpinv, *cwr, *cwi, *cmet, *cm0, *cm1, *cm2, *ccpost;
    bf16 *cq0r, *cq0i, *cq1r, *cq1i, *car, *cai, *csr, *csi;
    cudaGetSymbolAddress((void**)&cx,     c_x);
    cudaGetSymbolAddress((void**)&cwp,    c_wp);
    cudaGetSymbolAddress((void**)&cwpinv, c_wpinv);
    cudaGetSymbolAddress((void**)&cwr,    c_wr);
    cudaGetSymbolAddress((void**)&cwi,    c_wi);
    cudaGetSymbolAddress((void**)&cmet,   c_met);
    cudaGetSymbolAddress((void**)&cm0,    c_m0);
    cudaGetSymbolAddress((void**)&cm1,    c_m1);
    cudaGetSymbolAddress((void**)&cm2,    c_m2);
    cudaGetSymbolAddress((void**)&ccpost, c_cpost);
    cudaGetSymbolAddress((void**)&cq0r,   c_q0r);
    cudaGetSymbolAddress((void**)&cq0i,   c_q0i);
    cudaGetSymbolAddress((void**)&cq1r,   c_q1r);
    cudaGetSymbolAddress((void**)&cq1i,   c_q1i);
    cudaGetSymbolAddress((void**)&car,    c_ar);
    cudaGetSymbolAddress((void**)&cai,    c_ai);
    cudaGetSymbolAddress((void**)&csr,    c_sr);
    cudaGetSymbolAddress((void**)&csi,    c_si);

    cudaFuncSetAttribute(cgemm_kernel<true, false, false, true, true, false, true, false>,
                         cudaFuncAttributeMaxDynamicSharedMemorySize, SMEM_NT);
    cudaFuncSetAttribute(cgemm_kernel<true, false, true, true, true, false, true, false>,
                         cudaFuncAttributeMaxDynamicSharedMemorySize, SMEM_NT);
    cudaFuncSetAttribute(cgemm_kernel<true, true, true, true, true, true, false, true>,
                         cudaFuncAttributeMaxDynamicSharedMemorySize, SMEM_NT);
    cudaFuncSetAttribute(cgemm_kernel<false, false, true, false, true, false, true, false>,
                         cudaFuncAttributeMaxDynamicSharedMemorySize, SMEM_NN);
    cudaFuncSetAttribute(cgemm_kernel<false, false, true, true, true, false, true, false>,
                         cudaFuncAttributeMaxDynamicSharedMemorySize, SMEM_NN);
    cudaFuncSetAttribute(cgemm_kernel<false, false, true, true, false, false, true, false>,
                         cudaFuncAttributeMaxDynamicSharedMemorySize, SMEM_NN);

    const float scale = 0.03125f;                 // 1/sqrt(1024)
    const long long sQ = (long long)SEQ * MAN;
    const long long sS = (long long)SEQ * SEQ;
    const long long pMM = (long long)MAN * MAN;
    const long long pQ  = (long long)ROWS * MAN;
    const long long pS  = (long long)BATCH * SEQ * SEQ;
    const long long pW  = (long long)NLAYERS * pMM;   // batched weight plane stride

    conv(x, cx, (long long)ROWS * HID);
    conv(Wp, cwp, (long long)MAN * HID);
    conv(aWr, cwr, pW);                               // all 3 layers at once
    conv(aWi, cwi, pW);

    hgemm_b16_128(true, cx, (long long)ROWS * HID, cwp, (long long)MAN * HID,
                  cq0r, pQ, bp, ROWS, MAN, HID);

    bf16 *cqr = cq0r, *cqi = cq0i, *cqnr = cq1r, *cqni = cq1i;

    for (int l = 0; l < NLAYERS; l++) {
        const bf16* Wr = cwr + (long long)l * pMM;    // hi plane; lo at +pW
        const bf16* Wi = cwi + (long long)l * pMM;
        const float* br = abr + (long long)l * MAN;
        const float* bi = abi + (long long)l * MAN;

        // a = q (*) W^T + b
        {
            dim3 grid(MAN / 128, ROWS / 128, 1);
            if (l == 0)
                cgemm_kernel<true, false, false, true, true, false, true, false><<<grid, 256, SMEM_NT>>>(
                    cqr, cqi, pQ, Wr, Wi, pW,
                    nullptr, nullptr, car, cai, pQ, br, bi,
                    ROWS, MAN, MAN, 0, 0, 0, 1.f);
            else
                cgemm_kernel<true, false, true, true, true, false, true, false><<<grid, 256, SMEM_NT>>>(
                    cqr, cqi, pQ, Wr, Wi, pW,
                    nullptr, nullptr, car, cai, pQ, br, bi,
                    ROWS, MAN, MAN, 0, 0, 0, 1.f);
        }

        // scores = scale * a (*) conj(a)^T  (Hermitian triangular + mirror)
        {
            dim3 grid(136, 1, BATCH);
            cgemm_kernel<true, true, true, true, true, true, false, true><<<grid, 256, SMEM_NT>>>(
                car, cai, pQ, car, cai, pQ,
                sr, si, nullptr, nullptr, pS, nullptr, nullptr,
                SEQ, SEQ, MAN, sQ, sQ, sS, scale);
        }

        csoftmax_kernel<<<BATCH * SEQ, 256>>>(sr, si, csr, csi, pS);

        // q' = attn (*) q
        {
            dim3 grid(MAN / 128, SEQ / 128, BATCH);
            if (l == 0)
                cgemm_kernel<false, false, true, false, true, false, true, false><<<grid, 256, SMEM_NN>>>(
                    csr, csi, pS, cqr, cqi, pQ,
                    nullptr, nullptr, cqnr, cqni, pQ, nullptr, nullptr,
                    SEQ, MAN, SEQ, sS, sQ, sQ, 1.f);
            else if (l < NLAYERS - 1)
                cgemm_kernel<false, false, true, true, true, false, true, false><<<grid, 256, SMEM_NN>>>(
                    csr, csi, pS, cqr, cqi, pQ,
                    nullptr, nullptr, cqnr, cqni, pQ, nullptr, nullptr,
                    SEQ, MAN, SEQ, sS, sQ, sQ, 1.f);
            else
                cgemm_kernel<false, false, true, true, false, false, true, false><<<grid, 256, SMEM_NN>>>(
                    csr, csi, pS, cqr, cqi, pQ,
                    nullptr, nullptr, cqnr, cqni, pQ, nullptr, nullptr,
                    SEQ, MAN, SEQ, sS, sQ, sQ, 1.f);
        }

        bf16* tr = cqr; cqr = cqnr; cqnr = tr;
        bf16* ti = cqi; cqi = cqni; cqni = ti;
    }

    // ---- setup chain (BM=64 tiles, 128 CTAs each) ----
    conv(metric, cmet, pMM);
    conv(Wpinv, cwpinv, (long long)HID * MAN);
    {
        dim3 blk(16, 16), grd(MAN / 16, MAN / 16);
        build_mflow_kernel<<<grd, blk>>>(flowW, cm0, pMM);
    }
    hgemm_b16_64(false, cm0, pMM, cm0, pMM, cm1, pMM, MAN, MAN, MAN);   // Mf^2
    hgemm_b16_64(false, cm1, pMM, cm1, pMM, cm2, pMM, MAN, MAN, MAN);   // Mf^4
    hgemm_b16_64(false, cm2, pMM, cm2, pMM, cm0, pMM, MAN, MAN, MAN);   // Mf^8
    hgemm_b16_64(false, cm0, pMM, cm1, pMM, cm2, pMM, MAN, MAN, MAN);   // Mf^10
    hgemm_b16_64(false, cmet, pMM, cm2, pMM, cm1, pMM, MAN, MAN, MAN);  // g*Mf^10
    hgemm_b16_64(true, cm1, pMM, cwpinv, (long long)HID * MAN, ccpost,
                 (long long)MAN * HID, MAN, HID, MAN);                  // * Wpinv^T

    // ---- out = Re(q) @ Cpost + bp_inv ----
    hgemm_f32_nn(cqr, pQ, ccpost, (long long)MAN * HID, out, bpinv, ROWS, HID, MAN);
}

// round 12
// speedup vs baseline: 1.2365x; 1.0421x over previous
#include <cuda_runtime.h>
#include <cuda_bf16.h>
#include <stdint.h>
#include <math.h>

// ---------------------------------------------------------------------------
// QuantumGeometricAttention forward.  Fused complex HMMA GEMMs, bf16 hi/lo
// split (3 passes per real product), cp.async double buffering (BK=32),
// Hermitian scores (triangular + scatter mirror).  Setup chain (cpost) runs
// on a forked stream, overlapped with the attention layers.
// ---------------------------------------------------------------------------

#define BATCH 2
#define SEQ   2048
#define HID   1024
#define MAN   1024
#define ROWS  (BATCH * SEQ)
#define NLAYERS 3

typedef __nv_bfloat16 bf16;

// ---------------- fp32 scratch ----------------------------------------------
__device__ float g_sr [(size_t)BATCH * SEQ * SEQ];
__device__ float g_si [(size_t)BATCH * SEQ * SEQ];

// ---------------- bf16 hi/lo planes (hi at 0, lo at +plane) ------------------
__device__ bf16 c_x    [2 * (size_t)ROWS * HID];
__device__ bf16 c_wp   [2 * (size_t)MAN * HID];
__device__ bf16 c_wpinv[2 * (size_t)HID * MAN];
__device__ bf16 c_wr   [(size_t)NLAYERS * 2 * MAN * MAN];
__device__ bf16 c_wi   [(size_t)NLAYERS * 2 * MAN * MAN];
__device__ bf16 c_met  [2 * (size_t)MAN * MAN];
__device__ bf16 c_m0   [2 * (size_t)MAN * MAN];
__device__ bf16 c_m1   [2 * (size_t)MAN * MAN];
__device__ bf16 c_m2   [2 * (size_t)MAN * MAN];
__device__ bf16 c_cpost[2 * (size_t)MAN * HID];
__device__ bf16 c_q0r  [2 * (size_t)ROWS * MAN];
__device__ bf16 c_q0i  [2 * (size_t)ROWS * MAN];
__device__ bf16 c_q1r  [2 * (size_t)ROWS * MAN];
__device__ bf16 c_q1i  [2 * (size_t)ROWS * MAN];
__device__ bf16 c_ar   [2 * (size_t)ROWS * MAN];
__device__ bf16 c_ai   [2 * (size_t)ROWS * MAN];
__device__ bf16 c_sr   [2 * (size_t)BATCH * SEQ * SEQ];
__device__ bf16 c_si   [2 * (size_t)BATCH * SEQ * SEQ];

// ---------------------------- helpers ---------------------------------------
__device__ __forceinline__ uint32_t smem_u32(const void* p) {
    uint32_t a;
    asm("{ .reg .u64 t; cvta.to.shared.u64 t, %1; cvt.u32.u64 %0, t; }" : "=r"(a) : "l"(p));
    return a;
}
__device__ __forceinline__ void cp16(uint32_t dst, const void* src) {
    asm volatile("{ .reg .u64 g; cvta.to.global.u64 g, %1; cp.async.cg.shared.global [%0], [g], 16; }"
                 :: "r"(dst), "l"(src) : "memory");
}
#define CP_COMMIT() asm volatile("cp.async.commit_group;" ::: "memory")
#define CP_WAIT(n)  asm volatile("cp.async.wait_group %0;" :: "n"(n) : "memory")

#define MMA(d, a, b0, b1) \
    asm volatile("mma.sync.aligned.m16n8k16.row.col.f32.bf16.bf16.f32 " \
        "{%0,%1,%2,%3}, {%4,%5,%6,%7}, {%8,%9}, {%0,%1,%2,%3};" \
        : "+f"((d)[0]), "+f"((d)[1]), "+f"((d)[2]), "+f"((d)[3]) \
        : "r"((a)[0]), "r"((a)[1]), "r"((a)[2]), "r"((a)[3]), "r"(b0), "r"(b1))

__device__ __forceinline__ uint32_t pack_hi2(float a, float b, float& ra, float& rb) {
    bf16 h0 = __float2bfloat16(a), h1 = __float2bfloat16(b);
    ra = a - __bfloat162float(h0); rb = b - __bfloat162float(h1);
    return (uint32_t)__bfloat16_as_ushort(h0) | ((uint32_t)__bfloat16_as_ushort(h1) << 16);
}
__device__ __forceinline__ uint32_t pack2(float a, float b) {
    return (uint32_t)__bfloat16_as_ushort(__float2bfloat16(a)) |
           ((uint32_t)__bfloat16_as_ushort(__float2bfloat16(b)) << 16);
}

// ---------------------------------------------------------------------------
// fp32 -> bf16 hi/lo convert
// ---------------------------------------------------------------------------
__global__ __launch_bounds__(256)
void convert_hilo_kernel(const float* __restrict__ src, bf16* __restrict__ dst,
                         long long n4, long long plane)
{
    long long i = (long long)blockIdx.x * blockDim.x + threadIdx.x;
    if (i >= n4) return;
    float4 v = ((const float4*)src)[i];
    float r0, r1, r2, r3;
    uint2 hp, lp;
    hp.x = pack_hi2(v.x, v.y, r0, r1);
    hp.y = pack_hi2(v.z, v.w, r2, r3);
    lp.x = pack2(r0, r1);
    lp.y = pack2(r2, r3);
    ((uint2*)dst)[i] = hp;
    ((uint2*)(dst + plane))[i] = lp;
}

// ---------------------------------------------------------------------------
// Real HMMA GEMM (BK=32), bf16 hi/lo 3-pass; templated tile height BM.
// ---------------------------------------------------------------------------
template<bool TRANSB, bool WB16, int BM>
__global__ __launch_bounds__(256, 2)
void hgemm_kernel(const bf16* __restrict__ A, const bf16* __restrict__ B,
                  float* __restrict__ Cf, bf16* __restrict__ Cb, long long planeC,
                  const float* __restrict__ bias,
                  int M, int N, int K,
                  long long planeA, long long planeB,
                  float alpha)
{
    constexpr int MI = BM / 32;
    __shared__ __align__(16) bf16 sAm[2][BM][40];
    __shared__ __align__(16) bf16 sBm[2][5120];

    const int bm = blockIdx.y * BM;
    const int bn = blockIdx.x * 128;
    const int t = threadIdx.x, wid = t >> 5, lane = t & 31;
    const int wm = (wid >> 2) * (MI * 16), wn = (wid & 3) * 32;

    float acc[MI][4][4];
#pragma unroll
    for (int a = 0; a < MI; a++)
#pragma unroll
        for (int b = 0; b < 4; b++)
#pragma unroll
            for (int c = 0; c < 4; c++) acc[a][b][c] = 0.f;

    for (int k0 = 0; k0 < K; k0 += 32) {
        __syncthreads();
#pragma unroll
        for (int p = 0; p < 2; p++)
#pragma unroll
            for (int i = 0; i < BM / 64; i++) {
                int u = t + (i << 8);
                int r = u >> 2, kq = (u & 3) << 3;
                *(uint4*)&sAm[p][r][kq] =
                    *(const uint4*)(A + (long long)p * planeA + (long long)(bm + r) * K + k0 + kq);
            }
        if (TRANSB) {
#pragma unroll
            for (int p = 0; p < 2; p++)
#pragma unroll
                for (int i = 0; i < 2; i++) {
                    int u = t + (i << 8);
                    int r = u >> 2, kq = (u & 3) << 3;
                    *(uint4*)&sBm[p][r * 40 + kq] =
                        *(const uint4*)(B + (long long)p * planeB + (long long)(bn + r) * K + k0 + kq);
                }
        } else {
#pragma unroll
            for (int p = 0; p < 2; p++)
#pragma unroll
                for (int i = 0; i < 2; i++) {
                    int u = t + (i << 8);
                    int kr = u >> 4, nq = (u & 15) << 3;
                    *(uint4*)&sBm[p][kr * 136 + nq] =
                        *(const uint4*)(B + (long long)p * planeB + (long long)(k0 + kr) * N + bn + nq);
                }
        }
        __syncthreads();

#pragma unroll
        for (int kk = 0; kk < 2; kk++) {
            uint32_t Af[MI][4];
            uint32_t Bf[8];
            auto loadB = [&](int p) {
                if (TRANSB) {
                    uint32_t a0 = smem_u32(&sBm[p][(wn + ((lane >> 4) << 3) + (lane & 7)) * 40 + kk * 16 + (lane & 8)]);
                    asm volatile("ldmatrix.sync.aligned.m8n8.x4.shared.b16 {%0,%1,%2,%3}, [%4];"
                        : "=r"(Bf[0]), "=r"(Bf[1]), "=r"(Bf[2]), "=r"(Bf[3]) : "r"(a0));
                    uint32_t a1 = smem_u32(&sBm[p][(wn + 16 + ((lane >> 4) << 3) + (lane & 7)) * 40 + kk * 16 + (lane & 8)]);
                    asm volatile("ldmatrix.sync.aligned.m8n8.x4.shared.b16 {%0,%1,%2,%3}, [%4];"
                        : "=r"(Bf[4]), "=r"(Bf[5]), "=r"(Bf[6]), "=r"(Bf[7]) : "r"(a1));
                } else {
                    uint32_t a0 = smem_u32(&sBm[p][(kk * 16 + (lane & 7) + (lane & 8)) * 136 + wn + ((lane >> 4) << 3)]);
                    asm volatile("ldmatrix.sync.aligned.m8n8.x4.trans.shared.b16 {%0,%1,%2,%3}, [%4];"
                        : "=r"(Bf[0]), "=r"(Bf[1]), "=r"(Bf[2]), "=r"(Bf[3]) : "r"(a0));
                    uint32_t a1 = smem_u32(&sBm[p][(kk * 16 + (lane & 7) + (lane & 8)) * 136 + wn + 16 + ((lane >> 4) << 3)]);
                    asm volatile("ldmatrix.sync.aligned.m8n8.x4.trans.shared.b16 {%0,%1,%2,%3}, [%4];"
                        : "=r"(Bf[4]), "=r"(Bf[5]), "=r"(Bf[6]), "=r"(Bf[7]) : "r"(a1));
                }
            };
            auto loadA = [&](int p) {
#pragma unroll
                for (int mi = 0; mi < MI; mi++) {
                    uint32_t ad = smem_u32(&sAm[p][wm + mi * 16 + (lane & 15)][kk * 16 + ((lane >> 4) << 3)]);
                    asm volatile("ldmatrix.sync.aligned.m8n8.x4.shared.b16 {%0,%1,%2,%3}, [%4];"
                        : "=r"(Af[mi][0]), "=r"(Af[mi][1]), "=r"(Af[mi][2]), "=r"(Af[mi][3]) : "r"(ad));
                }
            };
            auto mmAll = [&]() {
#pragma unroll
                for (int mi = 0; mi < MI; mi++)
#pragma unroll
                    for (int nj = 0; nj < 4; nj++)
                        MMA(acc[mi][nj], Af[mi], Bf[2 * nj], Bf[2 * nj + 1]);
            };
            loadA(0); loadB(0); mmAll();
            loadB(1);           mmAll();
            loadA(1); loadB(0); mmAll();
        }
    }

#pragma unroll
    for (int mi = 0; mi < MI; mi++)
#pragma unroll
        for (int nj = 0; nj < 4; nj++) {
            int r0 = bm + wm + mi * 16 + (lane >> 2);
            int cc = bn + wn + nj * 8 + ((lane & 3) << 1);
            float2 bb = make_float2(0.f, 0.f);
            if (bias) bb = *(const float2*)(bias + cc);
#pragma unroll
            for (int h = 0; h < 2; h++) {
                long long off = (long long)(r0 + h * 8) * N + cc;
                float v0 = alpha * acc[mi][nj][2 * h + 0] + bb.x;
                float v1 = alpha * acc[mi][nj][2 * h + 1] + bb.y;
                if (WB16) {
                    float l0, l1;
                    *(uint32_t*)(Cb + off) = pack_hi2(v0, v1, l0, l1);
                    *(uint32_t*)(Cb + planeC + off) = pack2(l0, l1);
                } else {
                    *(float2*)(Cf + off) = make_float2(v0, v1);
                }
            }
        }
}

// ---------------------------------------------------------------------------
// Fused complex HMMA GEMM (BK=32, 12 passes for full complex).
//   HERM: lower-triangular tiles + scatter conjugate mirror.
// ---------------------------------------------------------------------------
#define APL 10240
#define BPL_NT 10240
#define BPL_NN 8704

template<bool TRANSB, bool CONJ, bool HAS_AI, bool HAS_BI, bool WANT_I,
         bool WF32, bool WB16, bool HERM>
__global__ __launch_bounds__(256, 1)
void cgemm_kernel(const bf16* __restrict__ Ar, const bf16* __restrict__ Ai, long long planeA,
                  const bf16* __restrict__ Br, const bf16* __restrict__ Bi, long long planeB,
                  float* __restrict__ CrF, float* __restrict__ CiF,
                  bf16* __restrict__ CrB, bf16* __restrict__ CiB, long long planeC,
                  const float* __restrict__ biasR, const float* __restrict__ biasI,
                  int M, int N, int K,
                  long long sA, long long sB, long long sC,
                  float alpha)
{
    extern __shared__ __align__(16) char smem[];
    constexpr int BPL = TRANSB ? BPL_NT : BPL_NN;
    constexpr int ASZ = 4 * APL;
    constexpr int STG = ASZ + 4 * BPL;

    const long long zb = blockIdx.z;
    Ar += zb * sA; if (HAS_AI) Ai += zb * sA;
    Br += zb * sB; if (HAS_BI) Bi += zb * sB;

    int bi, bj;
    if (HERM) {
        int bx = blockIdx.x;
        bi = (int)((sqrtf(8.f * bx + 1.f) - 1.f) * 0.5f);
        while ((bi + 1) * (bi + 2) / 2 <= bx) bi++;
        while (bi * (bi + 1) / 2 > bx) bi--;
        bj = bx - bi * (bi + 1) / 2;
    } else {
        bi = blockIdx.y; bj = blockIdx.x;
    }
    const int bm = bi * 128;
    const int bn = bj * 128;
    const int t = threadIdx.x, wid = t >> 5, lane = t & 31;
    const int wm = (wid >> 2) * 64, wn = (wid & 3) * 32;

    const uint32_t sbase = smem_u32(smem);
    const bf16* aps[4] = { Ar, Ar + planeA, Ai, HAS_AI ? (Ai + planeA) : Ai };
    const bf16* bps[4] = { Br, Br + planeB, Bi, HAS_BI ? (Bi + planeB) : Bi };
    const int NPA = HAS_AI ? 4 : 2;
    const int NPB = HAS_BI ? 4 : 2;

    auto issue = [&](int c, int buf) {
        const int k0 = c << 5;
        const uint32_t stg = sbase + (uint32_t)buf * STG;
        for (int p = 0; p < NPA; p++) {
#pragma unroll
            for (int i = 0; i < 2; i++) {
                int u = t + (i << 8);
                int r = u >> 2, cq = (u & 3) << 3;
                cp16(stg + p * APL + (r * 40 + cq) * 2,
                     aps[p] + (long long)(bm + r) * K + k0 + cq);
            }
        }
        if (TRANSB) {
            for (int p = 0; p < NPB; p++) {
#pragma unroll
                for (int i = 0; i < 2; i++) {
                    int u = t + (i << 8);
                    int r = u >> 2, cq = (u & 3) << 3;
                    cp16(stg + ASZ + p * BPL + (r * 40 + cq) * 2,
                         bps[p] + (long long)(bn + r) * K + k0 + cq);
                }
            }
        } else {
            for (int p = 0; p < NPB; p++) {
#pragma unroll
                for (int i = 0; i < 2; i++) {
                    int u = t + (i << 8);
                    int kr = u >> 4, nq = (u & 15) << 3;
                    cp16(stg + ASZ + p * BPL + (kr * 136 + nq) * 2,
                         bps[p] + (long long)(k0 + kr) * N + bn + nq);
                }
            }
        }
        CP_COMMIT();
    };

    float accR[4][4][4], accI[4][4][4];
#pragma unroll
    for (int a = 0; a < 4; a++)
#pragma unroll
        for (int b = 0; b < 4; b++)
#pragma unroll
            for (int c = 0; c < 4; c++) { accR[a][b][c] = 0.f; accI[a][b][c] = 0.f; }

    const int nch = K >> 5;
    issue(0, 0);

    for (int c = 0; c < nch; c++) {
        const int buf = c & 1;
        if (c + 1 < nch) { issue(c + 1, buf ^ 1); CP_WAIT(1); }
        else             { CP_WAIT(0); }
        __syncthreads();

        bf16* sAp = (bf16*)(smem + buf * STG);
        bf16* sBp = (bf16*)(smem + buf * STG + ASZ);

#pragma unroll
        for (int kk = 0; kk < 2; kk++) {
            uint32_t brh[8], brl[8], bih[8], bil[8];
            auto loadB = [&](int p, uint32_t* o) {
                bf16* bp = (bf16*)((char*)sBp + p * BPL);
                if (TRANSB) {
                    uint32_t a0 = smem_u32(&bp[(wn + ((lane >> 4) << 3) + (lane & 7)) * 40 + kk * 16 + (lane & 8)]);
                    asm volatile("ldmatrix.sync.aligned.m8n8.x4.shared.b16 {%0,%1,%2,%3}, [%4];"
                        : "=r"(o[0]), "=r"(o[1]), "=r"(o[2]), "=r"(o[3]) : "r"(a0));
                    uint32_t a1 = smem_u32(&bp[(wn + 16 + ((lane >> 4) << 3) + (lane & 7)) * 40 + kk * 16 + (lane & 8)]);
                    asm volatile("ldmatrix.sync.aligned.m8n8.x4.shared.b16 {%0,%1,%2,%3}, [%4];"
                        : "=r"(o[4]), "=r"(o[5]), "=r"(o[6]), "=r"(o[7]) : "r"(a1));
                } else {
                    uint32_t a0 = smem_u32(&bp[(kk * 16 + (lane & 7) + (lane & 8)) * 136 + wn + ((lane >> 4) << 3)]);
                    asm volatile("ldmatrix.sync.aligned.m8n8.x4.trans.shared.b16 {%0,%1,%2,%3}, [%4];"
                        : "=r"(o[0]), "=r"(o[1]), "=r"(o[2]), "=r"(o[3]) : "r"(a0));
                    uint32_t a1 = smem_u32(&bp[(kk * 16 + (lane & 7) + (lane & 8)) * 136 + wn + 16 + ((lane >> 4) << 3)]);
                    asm volatile("ldmatrix.sync.aligned.m8n8.x4.trans.shared.b16 {%0,%1,%2,%3}, [%4];"
                        : "=r"(o[4]), "=r"(o[5]), "=r"(o[6]), "=r"(o[7]) : "r"(a1));
                }
            };
            loadB(0, brh); loadB(1, brl);
            if (HAS_BI) { loadB(2, bih); loadB(3, bil); }

            uint32_t Af[4][4];
            auto loadA = [&](int p) {
                bf16* ap = (bf16*)((char*)sAp + p * APL);
#pragma unroll
                for (int mi = 0; mi < 4; mi++) {
                    uint32_t ad = smem_u32(&ap[(wm + mi * 16 + (lane & 15)) * 40 + kk * 16 + ((lane >> 4) << 3)]);
                    asm volatile("ldmatrix.sync.aligned.m8n8.x4.shared.b16 {%0,%1,%2,%3}, [%4];"
                        : "=r"(Af[mi][0]), "=r"(Af[mi][1]), "=r"(Af[mi][2]), "=r"(Af[mi][3]) : "r"(ad));
                }
            };
            auto negA = [&]() {
#pragma unroll
                for (int mi = 0; mi < 4; mi++)
#pragma unroll
                    for (int j = 0; j < 4; j++) Af[mi][j] ^= 0x80008000u;
            };
            auto mmP = [&](float (*acc)[4][4], const uint32_t* b) {
#pragma unroll
                for (int mi = 0; mi < 4; mi++)
#pragma unroll
                    for (int nj = 0; nj < 4; nj++)
                        MMA(acc[mi][nj], Af[mi], b[2 * nj], b[2 * nj + 1]);
            };

            loadA(0);
            mmP(accR, brh); mmP(accR, brl);
            if (WANT_I && HAS_BI) {
                if (CONJ) negA();
                mmP(accI, bih); mmP(accI, bil);
            }
            loadA(1);
            mmP(accR, brh);
            if (WANT_I && HAS_BI) { if (CONJ) negA(); mmP(accI, bih); }
            if (HAS_AI) {
                loadA(2);
                if (WANT_I) { mmP(accI, brh); mmP(accI, brl); }
                if (HAS_BI) {
                    if (!CONJ) negA();
                    mmP(accR, bih); mmP(accR, bil);
                }
                loadA(3);
                if (WANT_I) mmP(accI, brh);
                if (HAS_BI) { if (!CONJ) negA(); mmP(accR, bih); }
            }
        }
        __syncthreads();
    }

    // ---- epilogue (scatter mirror) ----
    float* crf = WF32 ? CrF + zb * sC : nullptr;
    float* cif = (WF32 && WANT_I) ? CiF + zb * sC : nullptr;
    bf16*  crb = WB16 ? CrB + zb * sC : nullptr;
    bf16*  cib = (WB16 && WANT_I) ? CiB + zb * sC : nullptr;
    const bool mirror = HERM && (bi != bj);

#pragma unroll
    for (int mi = 0; mi < 4; mi++)
#pragma unroll
        for (int nj = 0; nj < 4; nj++) {
            int r0 = bm + wm + mi * 16 + (lane >> 2);
            int cc = bn + wn + nj * 8 + ((lane & 3) << 1);
            float bR0 = 0.f, bR1 = 0.f, bI0 = 0.f, bI1 = 0.f;
            if (biasR) { bR0 = biasR[cc]; bR1 = biasR[cc + 1]; }
            if (WANT_I && biasI) { bI0 = biasI[cc]; bI1 = biasI[cc + 1]; }
#pragma unroll
            for (int h = 0; h < 2; h++) {
                long long row = r0 + h * 8;
                long long off = row * N + cc;
                float vr0 = alpha * accR[mi][nj][2 * h + 0] + bR0;
                float vr1 = alpha * accR[mi][nj][2 * h + 1] + bR1;
                float vi0 = 0.f, vi1 = 0.f;
                if (WANT_I) {
                    vi0 = alpha * accI[mi][nj][2 * h + 0] + bI0;
                    vi1 = alpha * accI[mi][nj][2 * h + 1] + bI1;
                }
                if (WF32) {
                    *(float2*)(crf + off) = make_float2(vr0, vr1);
                    if (WANT_I) *(float2*)(cif + off) = make_float2(vi0, vi1);
                    if (mirror) {
                        crf[(long long)cc * N + row] = vr0;
                        crf[(long long)(cc + 1) * N + row] = vr1;
                        if (WANT_I) {
                            cif[(long long)cc * N + row] = -vi0;
                            cif[(long long)(cc + 1) * N + row] = -vi1;
                        }
                    }
                }
                if (WB16) {
                    float l0, l1;
                    *(uint32_t*)(crb + off) = pack_hi2(vr0, vr1, l0, l1);
                    *(uint32_t*)(crb + planeC + off) = pack2(l0, l1);
                    if (WANT_I) {
                        *(uint32_t*)(cib + off) = pack_hi2(vi0, vi1, l0, l1);
                        *(uint32_t*)(cib + planeC + off) = pack2(l0, l1);
                    }
                }
            }
        }
}

// ---------------------------------------------------------------------------
// Complex softmax: fp32 (sr,si) in, bf16 hi/lo planes out.
// ---------------------------------------------------------------------------
__global__ __launch_bounds__(256)
void csoftmax_kernel(const float* __restrict__ sr, const float* __restrict__ si,
                     bf16* __restrict__ osr, bf16* __restrict__ osi, long long plane)
{
    const long long row = blockIdx.x;
    const float* pr = sr + row * (long long)SEQ;
    const float* pi = si + row * (long long)SEQ;
    const int t = threadIdx.x;
    const int i0 = t * 8;

    float vr[8], vi[8], mag[8], e[8];
    *(float4*)&vr[0] = *(const float4*)(pr + i0);
    *(float4*)&vr[4] = *(const float4*)(pr + i0 + 4);
    *(float4*)&vi[0] = *(const float4*)(pi + i0);
    *(float4*)&vi[4] = *(const float4*)(pi + i0 + 4);

    float mx = -1e30f;
#pragma unroll
    for (int i = 0; i < 8; i++) {
        mag[i] = sqrtf(vr[i] * vr[i] + vi[i] * vi[i]);
        mx = fmaxf(mx, mag[i]);
    }
    __shared__ float red[256];
    red[t] = mx; __syncthreads();
#pragma unroll
    for (int s = 128; s > 0; s >>= 1) {
        if (t < s) red[t] = fmaxf(red[t], red[t + s]);
        __syncthreads();
    }
    mx = red[0];
    __syncthreads();
    float sum = 0.f;
#pragma unroll
    for (int i = 0; i < 8; i++) { e[i] = expf(mag[i] - mx); sum += e[i]; }
    red[t] = sum; __syncthreads();
#pragma unroll
    for (int s = 128; s > 0; s >>= 1) {
        if (t < s) red[t] += red[t + s];
        __syncthreads();
    }
    sum = red[0];
    const float inv_s = 1.0f / (sum + 1e-8f);

    float orv[8], oiv[8];
#pragma unroll
    for (int i = 0; i < 8; i++) {
        float f = e[i] * inv_s / (mag[i] + 1e-8f);
        orv[i] = vr[i] * f; oiv[i] = vi[i] * f;
    }
    long long off = row * (long long)SEQ + i0;
    uint4 h, l;
    float r0, r1;
    h.x = pack_hi2(orv[0], orv[1], r0, r1); l.x = pack2(r0, r1);
    h.y = pack_hi2(orv[2], orv[3], r0, r1); l.y = pack2(r0, r1);
    h.z = pack_hi2(orv[4], orv[5], r0, r1); l.z = pack2(r0, r1);
    h.w = pack_hi2(orv[6], orv[7], r0, r1); l.w = pack2(r0, r1);
    *(uint4*)(osr + off) = h;
    *(uint4*)(osr + plane + off) = l;
    h.x = pack_hi2(oiv[0], oiv[1], r0, r1); l.x = pack2(r0, r1);
    h.y = pack_hi2(oiv[2], oiv[3], r0, r1); l.y = pack2(r0, r1);
    h.z = pack_hi2(oiv[4], oiv[5], r0, r1); l.z = pack2(r0, r1);
    h.w = pack_hi2(oiv[6], oiv[7], r0, r1); l.w = pack2(r0, r1);
    *(uint4*)(osi + off) = h;
    *(uint4*)(osi + plane + off) = l;
}

// Mf = 0.9*I + 0.1*flow_W  -> bf16 hi/lo planes directly
__global__ void build_mflow_kernel(const float* __restrict__ fw, bf16* __restrict__ mf,
                                   long long plane)
{
    int i = blockIdx.y * blockDim.y + threadIdx.y;
    int j = blockIdx.x * blockDim.x + threadIdx.x;
    float v = 0.1f * fw[(long long)i * MAN + j];
    if (i == j) v += 0.9f;
    bf16 h = __float2bfloat16(v);
    mf[(long long)i * MAN + j] = h;
    mf[plane + (long long)i * MAN + j] = __float2bfloat16(v - __bfloat162float(h));
}

// ---------------------------------------------------------------------------
// host-side
// ---------------------------------------------------------------------------
static void conv(const float* s, bf16* d, long long n, cudaStream_t st = 0)
{
    long long n4 = n / 4;
    convert_hilo_kernel<<<(unsigned)((n4 + 255) / 256), 256, 0, st>>>(s, d, n4, n);
}
static void hgemm_b16_128(bool transb, const bf16* A, long long pA, const bf16* B, long long pB,
                          bf16* C, long long pC, const float* bias, int M, int N, int K)
{
    dim3 grid(N / 128, M / 128, 1);
    if (transb) hgemm_kernel<true, true, 128><<<grid, 256>>>(A, B, nullptr, C, pC, bias, M, N, K, pA, pB, 1.f);
    else        hgemm_kernel<false, true, 128><<<grid, 256>>>(A, B, nullptr, C, pC, bias, M, N, K, pA, pB, 1.f);
}
static void hgemm_b16_64(bool transb, const bf16* A, long long pA, const bf16* B, long long pB,
                         bf16* C, long long pC, int M, int N, int K, cudaStream_t st)
{
    dim3 grid(N / 128, M / 64, 1);
    if (transb) hgemm_kernel<true, true, 64><<<grid, 256, 0, st>>>(A, B, nullptr, C, pC, nullptr, M, N, K, pA, pB, 1.f);
    else        hgemm_kernel<false, true, 64><<<grid, 256, 0, st>>>(A, B, nullptr, C, pC, nullptr, M, N, K, pA, pB, 1.f);
}
static void hgemm_f32_nn(const bf16* A, long long pA, const bf16* B, long long pB,
                         float* C, const float* bias, int M, int N, int K)
{
    dim3 grid(N / 128, M / 128, 1);
    hgemm_kernel<false, false, 128><<<grid, 256>>>(A, B, C, nullptr, 0, bias, M, N, K, pA, pB, 1.f);
}

#define SMEM_NT (2 * (4 * APL + 4 * BPL_NT))
#define SMEM_NN (2 * (4 * APL + 4 * BPL_NN))

extern "C" void kernel_launch(void* const* d_in, const int* in_sizes, int n_in,
                              void* d_out, int out_size)
{
    const float* x      = (const float*)d_in[0];
    const float* Wp     = (const float*)d_in[1];
    const float* bp     = (const float*)d_in[2];
    const float* Wpinv  = (const float*)d_in[3];
    const float* bpinv  = (const float*)d_in[4];
    const float* aWr    = (const float*)d_in[5];
    const float* aWi    = (const float*)d_in[6];
    const float* abr    = (const float*)d_in[7];
    const float* abi    = (const float*)d_in[8];
    const float* metric = (const float*)d_in[9];
    const float* flowW  = (const float*)d_in[10];
    float* out = (float*)d_out;

    float *sr, *si;
    cudaGetSymbolAddress((void**)&sr, g_sr);
    cudaGetSymbolAddress((void**)&si, g_si);

    bf16 *cx, *cwp, *cwpinv, *cwr, *cwi, *cmet, *cm0, *cm1, *cm2, *ccpost;
    bf16 *cq0r, *cq0i, *cq1r, *cq1i, *car, *cai, *csr, *csi;
    cudaGetSymbolAddress((void**)&cx,     c_x);
    cudaGetSymbolAddress((void**)&cwp,    c_wp);
    cudaGetSymbolAddress((void**)&cwpinv, c_wpinv);
    cudaGetSymbolAddress((void**)&cwr,    c_wr);
    cudaGetSymbolAddress((void**)&cwi,    c_wi);
    cudaGetSymbolAddress((void**)&cmet,   c_met);
    cudaGetSymbolAddress((void**)&cm0,    c_m0);
    cudaGetSymbolAddress((void**)&cm1,    c_m1);
    cudaGetSymbolAddress((void**)&cm2,    c_m2);
    cudaGetSymbolAddress((void**)&ccpost, c_cpost);
    cudaGetSymbolAddress((void**)&cq0r,   c_q0r);
    cudaGetSymbolAddress((void**)&cq0i,   c_q0i);
    cudaGetSymbolAddress((void**)&cq1r,   c_q1r);
    cudaGetSymbolAddress((void**)&cq1i,   c_q1i);
    cudaGetSymbolAddress((void**)&car,    c_ar);
    cudaGetSymbolAddress((void**)&cai,    c_ai);
    cudaGetSymbolAddress((void**)&csr,    c_sr);
    cudaGetSymbolAddress((void**)&csi,    c_si);

    cudaFuncSetAttribute(cgemm_kernel<true, false, false, true, true, false, true, false>,
                         cudaFuncAttributeMaxDynamicSharedMemorySize, SMEM_NT);
    cudaFuncSetAttribute(cgemm_kernel<true, false, true, true, true, false, true, false>,
                         cudaFuncAttributeMaxDynamicSharedMemorySize, SMEM_NT);
    cudaFuncSetAttribute(cgemm_kernel<true, true, true, true, true, true, false, true>,
                         cudaFuncAttributeMaxDynamicSharedMemorySize, SMEM_NT);
    cudaFuncSetAttribute(cgemm_kernel<false, false, true, false, true, false, true, false>,
                         cudaFuncAttributeMaxDynamicSharedMemorySize, SMEM_NN);
    cudaFuncSetAttribute(cgemm_kernel<false, false, true, true, true, false, true, false>,
                         cudaFuncAttributeMaxDynamicSharedMemorySize, SMEM_NN);
    cudaFuncSetAttribute(cgemm_kernel<false, false, true, true, false, false, true, false>,
                         cudaFuncAttributeMaxDynamicSharedMemorySize, SMEM_NN);

    // ---- fork/join infrastructure (created once; host-side objects only) ----
    static cudaStream_t s2 = nullptr;
    static cudaEvent_t evFork = nullptr, evJoin = nullptr;
    if (!s2) {
        cudaStreamCreateWithFlags(&s2, cudaStreamNonBlocking);
        cudaEventCreateWithFlags(&evFork, cudaEventDisableTiming);
        cudaEventCreateWithFlags(&evJoin, cudaEventDisableTiming);
    }

    const float scale = 0.03125f;                 // 1/sqrt(1024)
    const long long sQ = (long long)SEQ * MAN;
    const long long sS = (long long)SEQ * SEQ;
    const long long pMM = (long long)MAN * MAN;
    const long long pQ  = (long long)ROWS * MAN;
    const long long pS  = (long long)BATCH * SEQ * SEQ;
    const long long pW  = (long long)NLAYERS * pMM;

    // ---- fork: setup chain (cpost) runs concurrently on s2 ----
    cudaEventRecord(evFork, 0);
    cudaStreamWaitEvent(s2, evFork, 0);
    conv(metric, cmet, pMM, s2);
    conv(Wpinv, cwpinv, (long long)HID * MAN, s2);
    {
        dim3 blk(16, 16), grd(MAN / 16, MAN / 16);
        build_mflow_kernel<<<grd, blk, 0, s2>>>(flowW, cm0, pMM);
    }
    hgemm_b16_64(false, cm0, pMM, cm0, pMM, cm1, pMM, MAN, MAN, MAN, s2);   // Mf^2
    hgemm_b16_64(false, cm1, pMM, cm1, pMM, cm2, pMM, MAN, MAN, MAN, s2);   // Mf^4
    hgemm_b16_64(false, cm2, pMM, cm2, pMM, cm0, pMM, MAN, MAN, MAN, s2);   // Mf^8
    hgemm_b16_64(false, cm0, pMM, cm1, pMM, cm2, pMM, MAN, MAN, MAN, s2);   // Mf^10
    hgemm_b16_64(false, cmet, pMM, cm2, pMM, cm1, pMM, MAN, MAN, MAN, s2);  // g*Mf^10
    hgemm_b16_64(true, cm1, pMM, cwpinv, (long long)HID * MAN, ccpost,
                 (long long)MAN * HID, MAN, HID, MAN, s2);                  // * Wpinv^T
    cudaEventRecord(evJoin, s2);

    // ---- main path on default stream ----
    conv(x, cx, (long long)ROWS * HID);
    conv(Wp, cwp, (long long)MAN * HID);
    conv(aWr, cwr, pW);
    conv(aWi, cwi, pW);

    hgemm_b16_128(true, cx, (long long)ROWS * HID, cwp, (long long)MAN * HID,
                  cq0r, pQ, bp, ROWS, MAN, HID);

    bf16 *cqr = cq0r, *cqi = cq0i, *cqnr = cq1r, *cqni = cq1i;

    for (int l = 0; l < NLAYERS; l++) {
        const bf16* Wr = cwr + (long long)l * pMM;    // hi plane; lo at +pW
        const bf16* Wi = cwi + (long long)l * pMM;
        const float* br = abr + (long long)l * MAN;
        const float* bi = abi + (long long)l * MAN;

        // a = q (*) W^T + b
        {
            dim3 grid(MAN / 128, ROWS / 128, 1);
            if (l == 0)
                cgemm_kernel<true, false, false, true, true, false, true, false><<<grid, 256, SMEM_NT>>>(
                    cqr, cqi, pQ, Wr, Wi, pW,
                    nullptr, nullptr, car, cai, pQ, br, bi,
                    ROWS, MAN, MAN, 0, 0, 0, 1.f);
            else
                cgemm_kernel<true, false, true, true, true, false, true, false><<<grid, 256, SMEM_NT>>>(
                    cqr, cqi, pQ, Wr, Wi, pW,
                    nullptr, nullptr, car, cai, pQ, br, bi,
                    ROWS, MAN, MAN, 0, 0, 0, 1.f);
        }

        // scores = scale * a (*) conj(a)^T  (Hermitian triangular + mirror)
        {
            dim3 grid(136, 1, BATCH);
            cgemm_kernel<true, true, true, true, true, true, false, true><<<grid, 256, SMEM_NT>>>(
                car, cai, pQ, car, cai, pQ,
                sr, si, nullptr, nullptr, pS, nullptr, nullptr,
                SEQ, SEQ, MAN, sQ, sQ, sS, scale);
        }

        csoftmax_kernel<<<BATCH * SEQ, 256>>>(sr, si, csr, csi, pS);

        // q' = attn (*) q
        {
            dim3 grid(MAN / 128, SEQ / 128, BATCH);
            if (l == 0)
                cgemm_kernel<false, false, true, false, true, false, true, false><<<grid, 256, SMEM_NN>>>(
                    csr, csi, pS, cqr, cqi, pQ,
                    nullptr, nullptr, cqnr, cqni, pQ, nullptr, nullptr,
                    SEQ, MAN, SEQ, sS, sQ, sQ, 1.f);
            else if (l < NLAYERS - 1)
                cgemm_kernel<false, false, true, true, true, false, true, false><<<grid, 256, SMEM_NN>>>(
                    csr, csi, pS, cqr, cqi, pQ,
                    nullptr, nullptr, cqnr, cqni, pQ, nullptr, nullptr,
                    SEQ, MAN, SEQ, sS, sQ, sQ, 1.f);
            else
                cgemm_kernel<false, false, true, true, false, false, true, false><<<grid, 256, SMEM_NN>>>(
                    csr, csi, pS, cqr, cqi, pQ,
                    nullptr, nullptr, cqnr, cqni, pQ, nullptr, nullptr,
                    SEQ, MAN, SEQ, sS, sQ, sQ, 1.f);
        }

        bf16* tr = cqr; cqr = cqnr; cqnr = tr;
        bf16* ti = cqi; cqi = cqni; cqni = ti;
    }

    // ---- join: wait for cpost chain, then final projection ----
    cudaStreamWaitEvent(0, evJoin, 0);
    hgemm_f32_nn(cqr, pQ, ccpost, (long long)MAN * HID, out, bpinv, ROWS, HID, MAN);
}

// round 13
// speedup vs baseline: 1.2680x; 1.0255x over previous
#include <cuda_runtime.h>
#include <cuda_bf16.h>
#include <stdint.h>
#include <math.h>

// ---------------------------------------------------------------------------
// QuantumGeometricAttention forward.  Fused complex HMMA GEMMs, bf16 hi/lo
// split (3 passes per real product), cp.async single-sync pipeline (BK=32),
// Hermitian scores (triangular + scatter mirror), forked-stream setup chain.
// ---------------------------------------------------------------------------

#define BATCH 2
#define SEQ   2048
#define HID   1024
#define MAN   1024
#define ROWS  (BATCH * SEQ)
#define NLAYERS 3

typedef __nv_bfloat16 bf16;

// ---------------- fp32 scratch ----------------------------------------------
__device__ float g_sr [(size_t)BATCH * SEQ * SEQ];
__device__ float g_si [(size_t)BATCH * SEQ * SEQ];

// ---------------- bf16 hi/lo planes (hi at 0, lo at +plane) ------------------
__device__ bf16 c_x    [2 * (size_t)ROWS * HID];
__device__ bf16 c_wp   [2 * (size_t)MAN * HID];
__device__ bf16 c_wpinv[2 * (size_t)HID * MAN];
__device__ bf16 c_wr   [(size_t)NLAYERS * 2 * MAN * MAN];
__device__ bf16 c_wi   [(size_t)NLAYERS * 2 * MAN * MAN];
__device__ bf16 c_met  [2 * (size_t)MAN * MAN];
__device__ bf16 c_m0   [2 * (size_t)MAN * MAN];
__device__ bf16 c_m1   [2 * (size_t)MAN * MAN];
__device__ bf16 c_m2   [2 * (size_t)MAN * MAN];
__device__ bf16 c_cpost[2 * (size_t)MAN * HID];
__device__ bf16 c_q0r  [2 * (size_t)ROWS * MAN];
__device__ bf16 c_q0i  [2 * (size_t)ROWS * MAN];
__device__ bf16 c_q1r  [2 * (size_t)ROWS * MAN];
__device__ bf16 c_q1i  [2 * (size_t)ROWS * MAN];
__device__ bf16 c_ar   [2 * (size_t)ROWS * MAN];
__device__ bf16 c_ai   [2 * (size_t)ROWS * MAN];
__device__ bf16 c_sr   [2 * (size_t)BATCH * SEQ * SEQ];
__device__ bf16 c_si   [2 * (size_t)BATCH * SEQ * SEQ];

// ---------------------------- helpers ---------------------------------------
__device__ __forceinline__ uint32_t smem_u32(const void* p) {
    uint32_t a;
    asm("{ .reg .u64 t; cvta.to.shared.u64 t, %1; cvt.u32.u64 %0, t; }" : "=r"(a) : "l"(p));
    return a;
}
__device__ __forceinline__ void cp16(uint32_t dst, const void* src) {
    asm volatile("{ .reg .u64 g; cvta.to.global.u64 g, %1; cp.async.cg.shared.global [%0], [g], 16; }"
                 :: "r"(dst), "l"(src) : "memory");
}
#define CP_COMMIT() asm volatile("cp.async.commit_group;" ::: "memory")
#define CP_WAIT(n)  asm volatile("cp.async.wait_group %0;" :: "n"(n) : "memory")

#define MMA(d, a, b0, b1) \
    asm volatile("mma.sync.aligned.m16n8k16.row.col.f32.bf16.bf16.f32 " \
        "{%0,%1,%2,%3}, {%4,%5,%6,%7}, {%8,%9}, {%0,%1,%2,%3};" \
        : "+f"((d)[0]), "+f"((d)[1]), "+f"((d)[2]), "+f"((d)[3]) \
        : "r"((a)[0]), "r"((a)[1]), "r"((a)[2]), "r"((a)[3]), "r"(b0), "r"(b1))

__device__ __forceinline__ uint32_t pack_hi2(float a, float b, float& ra, float& rb) {
    bf16 h0 = __float2bfloat16(a), h1 = __float2bfloat16(b);
    ra = a - __bfloat162float(h0); rb = b - __bfloat162float(h1);
    return (uint32_t)__bfloat16_as_ushort(h0) | ((uint32_t)__bfloat16_as_ushort(h1) << 16);
}
__device__ __forceinline__ uint32_t pack2(float a, float b) {
    return (uint32_t)__bfloat16_as_ushort(__float2bfloat16(a)) |
           ((uint32_t)__bfloat16_as_ushort(__float2bfloat16(b)) << 16);
}

// ---------------------------------------------------------------------------
// fp32 -> bf16 hi/lo convert
// ---------------------------------------------------------------------------
__global__ __launch_bounds__(256)
void convert_hilo_kernel(const float* __restrict__ src, bf16* __restrict__ dst,
                         long long n4, long long plane)
{
    long long i = (long long)blockIdx.x * blockDim.x + threadIdx.x;
    if (i >= n4) return;
    float4 v = ((const float4*)src)[i];
    float r0, r1, r2, r3;
    uint2 hp, lp;
    hp.x = pack_hi2(v.x, v.y, r0, r1);
    hp.y = pack_hi2(v.z, v.w, r2, r3);
    lp.x = pack2(r0, r1);
    lp.y = pack2(r2, r3);
    ((uint2*)dst)[i] = hp;
    ((uint2*)(dst + plane))[i] = lp;
}

// ---------------------------------------------------------------------------
// Real HMMA GEMM (BK=32), bf16 hi/lo 3-pass; templated tile height BM.
// ---------------------------------------------------------------------------
template<bool TRANSB, bool WB16, int BM>
__global__ __launch_bounds__(256, 2)
void hgemm_kernel(const bf16* __restrict__ A, const bf16* __restrict__ B,
                  float* __restrict__ Cf, bf16* __restrict__ Cb, long long planeC,
                  const float* __restrict__ bias,
                  int M, int N, int K,
                  long long planeA, long long planeB,
                  float alpha)
{
    constexpr int MI = BM / 32;
    __shared__ __align__(16) bf16 sAm[2][BM][40];
    __shared__ __align__(16) bf16 sBm[2][5120];

    const int bm = blockIdx.y * BM;
    const int bn = blockIdx.x * 128;
    const int t = threadIdx.x, wid = t >> 5, lane = t & 31;
    const int wm = (wid >> 2) * (MI * 16), wn = (wid & 3) * 32;

    float acc[MI][4][4];
#pragma unroll
    for (int a = 0; a < MI; a++)
#pragma unroll
        for (int b = 0; b < 4; b++)
#pragma unroll
            for (int c = 0; c < 4; c++) acc[a][b][c] = 0.f;

    for (int k0 = 0; k0 < K; k0 += 32) {
        __syncthreads();
#pragma unroll
        for (int p = 0; p < 2; p++)
#pragma unroll
            for (int i = 0; i < BM / 64; i++) {
                int u = t + (i << 8);
                int r = u >> 2, kq = (u & 3) << 3;
                *(uint4*)&sAm[p][r][kq] =
                    *(const uint4*)(A + (long long)p * planeA + (long long)(bm + r) * K + k0 + kq);
            }
        if (TRANSB) {
#pragma unroll
            for (int p = 0; p < 2; p++)
#pragma unroll
                for (int i = 0; i < 2; i++) {
                    int u = t + (i << 8);
                    int r = u >> 2, kq = (u & 3) << 3;
                    *(uint4*)&sBm[p][r * 40 + kq] =
                        *(const uint4*)(B + (long long)p * planeB + (long long)(bn + r) * K + k0 + kq);
                }
        } else {
#pragma unroll
            for (int p = 0; p < 2; p++)
#pragma unroll
                for (int i = 0; i < 2; i++) {
                    int u = t + (i << 8);
                    int kr = u >> 4, nq = (u & 15) << 3;
                    *(uint4*)&sBm[p][kr * 136 + nq] =
                        *(const uint4*)(B + (long long)p * planeB + (long long)(k0 + kr) * N + bn + nq);
                }
        }
        __syncthreads();

#pragma unroll
        for (int kk = 0; kk < 2; kk++) {
            uint32_t Af[MI][4];
            uint32_t Bf[8];
            auto loadB = [&](int p) {
                if (TRANSB) {
                    uint32_t a0 = smem_u32(&sBm[p][(wn + ((lane >> 4) << 3) + (lane & 7)) * 40 + kk * 16 + (lane & 8)]);
                    asm volatile("ldmatrix.sync.aligned.m8n8.x4.shared.b16 {%0,%1,%2,%3}, [%4];"
                        : "=r"(Bf[0]), "=r"(Bf[1]), "=r"(Bf[2]), "=r"(Bf[3]) : "r"(a0));
                    uint32_t a1 = smem_u32(&sBm[p][(wn + 16 + ((lane >> 4) << 3) + (lane & 7)) * 40 + kk * 16 + (lane & 8)]);
                    asm volatile("ldmatrix.sync.aligned.m8n8.x4.shared.b16 {%0,%1,%2,%3}, [%4];"
                        : "=r"(Bf[4]), "=r"(Bf[5]), "=r"(Bf[6]), "=r"(Bf[7]) : "r"(a1));
                } else {
                    uint32_t a0 = smem_u32(&sBm[p][(kk * 16 + (lane & 7) + (lane & 8)) * 136 + wn + ((lane >> 4) << 3)]);
                    asm volatile("ldmatrix.sync.aligned.m8n8.x4.trans.shared.b16 {%0,%1,%2,%3}, [%4];"
                        : "=r"(Bf[0]), "=r"(Bf[1]), "=r"(Bf[2]), "=r"(Bf[3]) : "r"(a0));
                    uint32_t a1 = smem_u32(&sBm[p][(kk * 16 + (lane & 7) + (lane & 8)) * 136 + wn + 16 + ((lane >> 4) << 3)]);
                    asm volatile("ldmatrix.sync.aligned.m8n8.x4.trans.shared.b16 {%0,%1,%2,%3}, [%4];"
                        : "=r"(Bf[4]), "=r"(Bf[5]), "=r"(Bf[6]), "=r"(Bf[7]) : "r"(a1));
                }
            };
            auto loadA = [&](int p) {
#pragma unroll
                for (int mi = 0; mi < MI; mi++) {
                    uint32_t ad = smem_u32(&sAm[p][wm + mi * 16 + (lane & 15)][kk * 16 + ((lane >> 4) << 3)]);
                    asm volatile("ldmatrix.sync.aligned.m8n8.x4.shared.b16 {%0,%1,%2,%3}, [%4];"
                        : "=r"(Af[mi][0]), "=r"(Af[mi][1]), "=r"(Af[mi][2]), "=r"(Af[mi][3]) : "r"(ad));
                }
            };
            auto mmAll = [&]() {
#pragma unroll
                for (int mi = 0; mi < MI; mi++)
#pragma unroll
                    for (int nj = 0; nj < 4; nj++)
                        MMA(acc[mi][nj], Af[mi], Bf[2 * nj], Bf[2 * nj + 1]);
            };
            loadA(0); loadB(0); mmAll();
            loadB(1);           mmAll();
            loadA(1); loadB(0); mmAll();
        }
    }

#pragma unroll
    for (int mi = 0; mi < MI; mi++)
#pragma unroll
        for (int nj = 0; nj < 4; nj++) {
            int r0 = bm + wm + mi * 16 + (lane >> 2);
            int cc = bn + wn + nj * 8 + ((lane & 3) << 1);
            float2 bb = make_float2(0.f, 0.f);
            if (bias) bb = *(const float2*)(bias + cc);
#pragma unroll
            for (int h = 0; h < 2; h++) {
                long long off = (long long)(r0 + h * 8) * N + cc;
                float v0 = alpha * acc[mi][nj][2 * h + 0] + bb.x;
                float v1 = alpha * acc[mi][nj][2 * h + 1] + bb.y;
                if (WB16) {
                    float l0, l1;
                    *(uint32_t*)(Cb + off) = pack_hi2(v0, v1, l0, l1);
                    *(uint32_t*)(Cb + planeC + off) = pack2(l0, l1);
                } else {
                    *(float2*)(Cf + off) = make_float2(v0, v1);
                }
            }
        }
}

// ---------------------------------------------------------------------------
// Fused complex HMMA GEMM (BK=32, 12 passes for full complex).
//   Single-sync cp.async pipeline: CP_WAIT -> sync -> issue(next) -> compute.
//   HERM: lower-triangular tiles + scatter conjugate mirror.
// ---------------------------------------------------------------------------
#define APL 10240
#define BPL_NT 10240
#define BPL_NN 8704

template<bool TRANSB, bool CONJ, bool HAS_AI, bool HAS_BI, bool WANT_I,
         bool WF32, bool WB16, bool HERM>
__global__ __launch_bounds__(256, 1)
void cgemm_kernel(const bf16* __restrict__ Ar, const bf16* __restrict__ Ai, long long planeA,
                  const bf16* __restrict__ Br, const bf16* __restrict__ Bi, long long planeB,
                  float* __restrict__ CrF, float* __restrict__ CiF,
                  bf16* __restrict__ CrB, bf16* __restrict__ CiB, long long planeC,
                  const float* __restrict__ biasR, const float* __restrict__ biasI,
                  int M, int N, int K,
                  long long sA, long long sB, long long sC,
                  float alpha)
{
    extern __shared__ __align__(16) char smem[];
    constexpr int BPL = TRANSB ? BPL_NT : BPL_NN;
    constexpr int ASZ = 4 * APL;
    constexpr int STG = ASZ + 4 * BPL;

    const long long zb = blockIdx.z;
    Ar += zb * sA; if (HAS_AI) Ai += zb * sA;
    Br += zb * sB; if (HAS_BI) Bi += zb * sB;

    int bi, bj;
    if (HERM) {
        int bx = blockIdx.x;
        bi = (int)((sqrtf(8.f * bx + 1.f) - 1.f) * 0.5f);
        while ((bi + 1) * (bi + 2) / 2 <= bx) bi++;
        while (bi * (bi + 1) / 2 > bx) bi--;
        bj = bx - bi * (bi + 1) / 2;
    } else {
        bi = blockIdx.y; bj = blockIdx.x;
    }
    const int bm = bi * 128;
    const int bn = bj * 128;
    const int t = threadIdx.x, wid = t >> 5, lane = t & 31;
    const int wm = (wid >> 2) * 64, wn = (wid & 3) * 32;

    const uint32_t sbase = smem_u32(smem);
    const bf16* aps[4] = { Ar, Ar + planeA, Ai, HAS_AI ? (Ai + planeA) : Ai };
    const bf16* bps[4] = { Br, Br + planeB, Bi, HAS_BI ? (Bi + planeB) : Bi };
    const int NPA = HAS_AI ? 4 : 2;
    const int NPB = HAS_BI ? 4 : 2;

    auto issue = [&](int c, int buf) {
        const int k0 = c << 5;
        const uint32_t stg = sbase + (uint32_t)buf * STG;
        for (int p = 0; p < NPA; p++) {
#pragma unroll
            for (int i = 0; i < 2; i++) {
                int u = t + (i << 8);
                int r = u >> 2, cq = (u & 3) << 3;
                cp16(stg + p * APL + (r * 40 + cq) * 2,
                     aps[p] + (long long)(bm + r) * K + k0 + cq);
            }
        }
        if (TRANSB) {
            for (int p = 0; p < NPB; p++) {
#pragma unroll
                for (int i = 0; i < 2; i++) {
                    int u = t + (i << 8);
                    int r = u >> 2, cq = (u & 3) << 3;
                    cp16(stg + ASZ + p * BPL + (r * 40 + cq) * 2,
                         bps[p] + (long long)(bn + r) * K + k0 + cq);
                }
            }
        } else {
            for (int p = 0; p < NPB; p++) {
#pragma unroll
                for (int i = 0; i < 2; i++) {
                    int u = t + (i << 8);
                    int kr = u >> 4, nq = (u & 15) << 3;
                    cp16(stg + ASZ + p * BPL + (kr * 136 + nq) * 2,
                         bps[p] + (long long)(k0 + kr) * N + bn + nq);
                }
            }
        }
        CP_COMMIT();
    };

    float accR[4][4][4], accI[4][4][4];
#pragma unroll
    for (int a = 0; a < 4; a++)
#pragma unroll
        for (int b = 0; b < 4; b++)
#pragma unroll
            for (int c = 0; c < 4; c++) { accR[a][b][c] = 0.f; accI[a][b][c] = 0.f; }

    const int nch = K >> 5;
    issue(0, 0);

    for (int c = 0; c < nch; c++) {
        const int buf = c & 1;
        CP_WAIT(0);              // chunk c data arrived (only group in flight)
        __syncthreads();         // data visible + all warps done with buf^1
        if (c + 1 < nch) issue(c + 1, buf ^ 1);

        bf16* sAp = (bf16*)(smem + buf * STG);
        bf16* sBp = (bf16*)(smem + buf * STG + ASZ);

#pragma unroll
        for (int kk = 0; kk < 2; kk++) {
            uint32_t brh[8], brl[8], bih[8], bil[8];
            auto loadB = [&](int p, uint32_t* o) {
                bf16* bp = (bf16*)((char*)sBp + p * BPL);
                if (TRANSB) {
                    uint32_t a0 = smem_u32(&bp[(wn + ((lane >> 4) << 3) + (lane & 7)) * 40 + kk * 16 + (lane & 8)]);
                    asm volatile("ldmatrix.sync.aligned.m8n8.x4.shared.b16 {%0,%1,%2,%3}, [%4];"
                        : "=r"(o[0]), "=r"(o[1]), "=r"(o[2]), "=r"(o[3]) : "r"(a0));
                    uint32_t a1 = smem_u32(&bp[(wn + 16 + ((lane >> 4) << 3) + (lane & 7)) * 40 + kk * 16 + (lane & 8)]);
                    asm volatile("ldmatrix.sync.aligned.m8n8.x4.shared.b16 {%0,%1,%2,%3}, [%4];"
                        : "=r"(o[4]), "=r"(o[5]), "=r"(o[6]), "=r"(o[7]) : "r"(a1));
                } else {
                    uint32_t a0 = smem_u32(&bp[(kk * 16 + (lane & 7) + (lane & 8)) * 136 + wn + ((lane >> 4) << 3)]);
                    asm volatile("ldmatrix.sync.aligned.m8n8.x4.trans.shared.b16 {%0,%1,%2,%3}, [%4];"
                        : "=r"(o[0]), "=r"(o[1]), "=r"(o[2]), "=r"(o[3]) : "r"(a0));
                    uint32_t a1 = smem_u32(&bp[(kk * 16 + (lane & 7) + (lane & 8)) * 136 + wn + 16 + ((lane >> 4) << 3)]);
                    asm volatile("ldmatrix.sync.aligned.m8n8.x4.trans.shared.b16 {%0,%1,%2,%3}, [%4];"
                        : "=r"(o[4]), "=r"(o[5]), "=r"(o[6]), "=r"(o[7]) : "r"(a1));
                }
            };
            loadB(0, brh); loadB(1, brl);
            if (HAS_BI) { loadB(2, bih); loadB(3, bil); }

            uint32_t Af[4][4];
            auto loadA = [&](int p) {
                bf16* ap = (bf16*)((char*)sAp + p * APL);
#pragma unroll
                for (int mi = 0; mi < 4; mi++) {
                    uint32_t ad = smem_u32(&ap[(wm + mi * 16 + (lane & 15)) * 40 + kk * 16 + ((lane >> 4) << 3)]);
                    asm volatile("ldmatrix.sync.aligned.m8n8.x4.shared.b16 {%0,%1,%2,%3}, [%4];"
                        : "=r"(Af[mi][0]), "=r"(Af[mi][1]), "=r"(Af[mi][2]), "=r"(Af[mi][3]) : "r"(ad));
                }
            };
            auto negA = [&]() {
#pragma unroll
                for (int mi = 0; mi < 4; mi++)
#pragma unroll
                    for (int j = 0; j < 4; j++) Af[mi][j] ^= 0x80008000u;
            };
            auto mmP = [&](float (*acc)[4][4], const uint32_t* b) {
#pragma unroll
                for (int mi = 0; mi < 4; mi++)
#pragma unroll
                    for (int nj = 0; nj < 4; nj++)
                        MMA(acc[mi][nj], Af[mi], b[2 * nj], b[2 * nj + 1]);
            };

            loadA(0);
            mmP(accR, brh); mmP(accR, brl);
            if (WANT_I && HAS_BI) {
                if (CONJ) negA();
                mmP(accI, bih); mmP(accI, bil);
            }
            loadA(1);
            mmP(accR, brh);
            if (WANT_I && HAS_BI) { if (CONJ) negA(); mmP(accI, bih); }
            if (HAS_AI) {
                loadA(2);
                if (WANT_I) { mmP(accI, brh); mmP(accI, brl); }
                if (HAS_BI) {
                    if (!CONJ) negA();
                    mmP(accR, bih); mmP(accR, bil);
                }
                loadA(3);
                if (WANT_I) mmP(accI, brh);
                if (HAS_BI) { if (!CONJ) negA(); mmP(accR, bih); }
            }
        }
    }

    // ---- epilogue (scatter mirror) ----
    float* crf = WF32 ? CrF + zb * sC : nullptr;
    float* cif = (WF32 && WANT_I) ? CiF + zb * sC : nullptr;
    bf16*  crb = WB16 ? CrB + zb * sC : nullptr;
    bf16*  cib = (WB16 && WANT_I) ? CiB + zb * sC : nullptr;
    const bool mirror = HERM && (bi != bj);

#pragma unroll
    for (int mi = 0; mi < 4; mi++)
#pragma unroll
        for (int nj = 0; nj < 4; nj++) {
            int r0 = bm + wm + mi * 16 + (lane >> 2);
            int cc = bn + wn + nj * 8 + ((lane & 3) << 1);
            float bR0 = 0.f, bR1 = 0.f, bI0 = 0.f, bI1 = 0.f;
            if (biasR) { bR0 = biasR[cc]; bR1 = biasR[cc + 1]; }
            if (WANT_I && biasI) { bI0 = biasI[cc]; bI1 = biasI[cc + 1]; }
#pragma unroll
            for (int h = 0; h < 2; h++) {
                long long row = r0 + h * 8;
                long long off = row * N + cc;
                float vr0 = alpha * accR[mi][nj][2 * h + 0] + bR0;
                float vr1 = alpha * accR[mi][nj][2 * h + 1] + bR1;
                float vi0 = 0.f, vi1 = 0.f;
                if (WANT_I) {
                    vi0 = alpha * accI[mi][nj][2 * h + 0] + bI0;
                    vi1 = alpha * accI[mi][nj][2 * h + 1] + bI1;
                }
                if (WF32) {
                    *(float2*)(crf + off) = make_float2(vr0, vr1);
                    if (WANT_I) *(float2*)(cif + off) = make_float2(vi0, vi1);
                    if (mirror) {
                        crf[(long long)cc * N + row] = vr0;
                        crf[(long long)(cc + 1) * N + row] = vr1;
                        if (WANT_I) {
                            cif[(long long)cc * N + row] = -vi0;
                            cif[(long long)(cc + 1) * N + row] = -vi1;
                        }
                    }
                }
                if (WB16) {
                    float l0, l1;
                    *(uint32_t*)(crb + off) = pack_hi2(vr0, vr1, l0, l1);
                    *(uint32_t*)(crb + planeC + off) = pack2(l0, l1);
                    if (WANT_I) {
                        *(uint32_t*)(cib + off) = pack_hi2(vi0, vi1, l0, l1);
                        *(uint32_t*)(cib + planeC + off) = pack2(l0, l1);
                    }
                }
            }
        }
}

// ---------------------------------------------------------------------------
// Complex softmax: fp32 (sr,si) in, bf16 hi/lo planes out.
// ---------------------------------------------------------------------------
__global__ __launch_bounds__(256)
void csoftmax_kernel(const float* __restrict__ sr, const float* __restrict__ si,
                     bf16* __restrict__ osr, bf16* __restrict__ osi, long long plane)
{
    const long long row = blockIdx.x;
    const float* pr = sr + row * (long long)SEQ;
    const float* pi = si + row * (long long)SEQ;
    const int t = threadIdx.x;
    const int i0 = t * 8;

    float vr[8], vi[8], mag[8], e[8];
    *(float4*)&vr[0] = *(const float4*)(pr + i0);
    *(float4*)&vr[4] = *(const float4*)(pr + i0 + 4);
    *(float4*)&vi[0] = *(const float4*)(pi + i0);
    *(float4*)&vi[4] = *(const float4*)(pi + i0 + 4);

    float mx = -1e30f;
#pragma unroll
    for (int i = 0; i < 8; i++) {
        mag[i] = sqrtf(vr[i] * vr[i] + vi[i] * vi[i]);
        mx = fmaxf(mx, mag[i]);
    }
    __shared__ float red[256];
    red[t] = mx; __syncthreads();
#pragma unroll
    for (int s = 128; s > 0; s >>= 1) {
        if (t < s) red[t] = fmaxf(red[t], red[t + s]);
        __syncthreads();
    }
    mx = red[0];
    __syncthreads();
    float sum = 0.f;
#pragma unroll
    for (int i = 0; i < 8; i++) { e[i] = expf(mag[i] - mx); sum += e[i]; }
    red[t] = sum; __syncthreads();
#pragma unroll
    for (int s = 128; s > 0; s >>= 1) {
        if (t < s) red[t] += red[t + s];
        __syncthreads();
    }
    sum = red[0];
    const float inv_s = 1.0f / (sum + 1e-8f);

    float orv[8], oiv[8];
#pragma unroll
    for (int i = 0; i < 8; i++) {
        float f = e[i] * inv_s / (mag[i] + 1e-8f);
        orv[i] = vr[i] * f; oiv[i] = vi[i] * f;
    }
    long long off = row * (long long)SEQ + i0;
    uint4 h, l;
    float r0, r1;
    h.x = pack_hi2(orv[0], orv[1], r0, r1); l.x = pack2(r0, r1);
    h.y = pack_hi2(orv[2], orv[3], r0, r1); l.y = pack2(r0, r1);
    h.z = pack_hi2(orv[4], orv[5], r0, r1); l.z = pack2(r0, r1);
    h.w = pack_hi2(orv[6], orv[7], r0, r1); l.w = pack2(r0, r1);
    *(uint4*)(osr + off) = h;
    *(uint4*)(osr + plane + off) = l;
    h.x = pack_hi2(oiv[0], oiv[1], r0, r1); l.x = pack2(r0, r1);
    h.y = pack_hi2(oiv[2], oiv[3], r0, r1); l.y = pack2(r0, r1);
    h.z = pack_hi2(oiv[4], oiv[5], r0, r1); l.z = pack2(r0, r1);
    h.w = pack_hi2(oiv[6], oiv[7], r0, r1); l.w = pack2(r0, r1);
    *(uint4*)(osi + off) = h;
    *(uint4*)(osi + plane + off) = l;
}

// Mf = 0.9*I + 0.1*flow_W  -> bf16 hi/lo planes directly
__global__ void build_mflow_kernel(const float* __restrict__ fw, bf16* __restrict__ mf,
                                   long long plane)
{
    int i = blockIdx.y * blockDim.y + threadIdx.y;
    int j = blockIdx.x * blockDim.x + threadIdx.x;
    float v = 0.1f * fw[(long long)i * MAN + j];
    if (i == j) v += 0.9f;
    bf16 h = __float2bfloat16(v);
    mf[(long long)i * MAN + j] = h;
    mf[plane + (long long)i * MAN + j] = __float2bfloat16(v - __bfloat162float(h));
}

// ---------------------------------------------------------------------------
// host-side
// ---------------------------------------------------------------------------
static void conv(const float* s, bf16* d, long long n, cudaStream_t st = 0)
{
    long long n4 = n / 4;
    convert_hilo_kernel<<<(unsigned)((n4 + 255) / 256), 256, 0, st>>>(s, d, n4, n);
}
static void hgemm_b16_128(bool transb, const bf16* A, long long pA, const bf16* B, long long pB,
                          bf16* C, long long pC, const float* bias, int M, int N, int K)
{
    dim3 grid(N / 128, M / 128, 1);
    if (transb) hgemm_kernel<true, true, 128><<<grid, 256>>>(A, B, nullptr, C, pC, bias, M, N, K, pA, pB, 1.f);
    else        hgemm_kernel<false, true, 128><<<grid, 256>>>(A, B, nullptr, C, pC, bias, M, N, K, pA, pB, 1.f);
}
static void hgemm_b16_64(bool transb, const bf16* A, long long pA, const bf16* B, long long pB,
                         bf16* C, long long pC, int M, int N, int K, cudaStream_t st)
{
    dim3 grid(N / 128, M / 64, 1);
    if (transb) hgemm_kernel<true, true, 64><<<grid, 256, 0, st>>>(A, B, nullptr, C, pC, nullptr, M, N, K, pA, pB, 1.f);
    else        hgemm_kernel<false, true, 64><<<grid, 256, 0, st>>>(A, B, nullptr, C, pC, nullptr, M, N, K, pA, pB, 1.f);
}
static void hgemm_f32_nn(const bf16* A, long long pA, const bf16* B, long long pB,
                         float* C, const float* bias, int M, int N, int K)
{
    dim3 grid(N / 128, M / 128, 1);
    hgemm_kernel<false, false, 128><<<grid, 256>>>(A, B, C, nullptr, 0, bias, M, N, K, pA, pB, 1.f);
}

#define SMEM_NT (2 * (4 * APL + 4 * BPL_NT))
#define SMEM_NN (2 * (4 * APL + 4 * BPL_NN))

extern "C" void kernel_launch(void* const* d_in, const int* in_sizes, int n_in,
                              void* d_out, int out_size)
{
    const float* x      = (const float*)d_in[0];
    const float* Wp     = (const float*)d_in[1];
    const float* bp     = (const float*)d_in[2];
    const float* Wpinv  = (const float*)d_in[3];
    const float* bpinv  = (const float*)d_in[4];
    const float* aWr    = (const float*)d_in[5];
    const float* aWi    = (const float*)d_in[6];
    const float* abr    = (const float*)d_in[7];
    const float* abi    = (const float*)d_in[8];
    const float* metric = (const float*)d_in[9];
    const float* flowW  = (const float*)d_in[10];
    float* out = (float*)d_out;

    float *sr, *si;
    cudaGetSymbolAddress((void**)&sr, g_sr);
    cudaGetSymbolAddress((void**)&si, g_si);

    bf16 *cx, *cwp, *cwpinv, *cwr, *cwi, *cmet, *cm0, *cm1, *cm2, *ccpost;
    bf16 *cq0r, *cq0i, *cq1r, *cq1i, *car, *cai, *csr, *csi;
    cudaGetSymbolAddress((void**)&cx,     c_x);
    cudaGetSymbolAddress((void**)&cwp,    c_wp);
    cudaGetSymbolAddress((void**)&cwpinv, c_wpinv);
    cudaGetSymbolAddress((void**)&cwr,    c_wr);
    cudaGetSymbolAddress((void**)&cwi,    c_wi);
    cudaGetSymbolAddress((void**)&cmet,   c_met);
    cudaGetSymbolAddress((void**)&cm0,    c_m0);
    cudaGetSymbolAddress((void**)&cm1,    c_m1);
    cudaGetSymbolAddress((void**)&cm2,    c_m2);
    cudaGetSymbolAddress((void**)&ccpost, c_cpost);
    cudaGetSymbolAddress((void**)&cq0r,   c_q0r);
    cudaGetSymbolAddress((void**)&cq0i,   c_q0i);
    cudaGetSymbolAddress((void**)&cq1r,   c_q1r);
    cudaGetSymbolAddress((void**)&cq1i,   c_q1i);
    cudaGetSymbolAddress((void**)&car,    c_ar);
    cudaGetSymbolAddress((void**)&cai,    c_ai);
    cudaGetSymbolAddress((void**)&csr,    c_sr);
    cudaGetSymbolAddress((void**)&csi,    c_si);

    cudaFuncSetAttribute(cgemm_kernel<true, false, false, true, true, false, true, false>,
                         cudaFuncAttributeMaxDynamicSharedMemorySize, SMEM_NT);
    cudaFuncSetAttribute(cgemm_kernel<true, false, true, true, true, false, true, false>,
                         cudaFuncAttributeMaxDynamicSharedMemorySize, SMEM_NT);
    cudaFuncSetAttribute(cgemm_kernel<true, true, true, true, true, true, false, true>,
                         cudaFuncAttributeMaxDynamicSharedMemorySize, SMEM_NT);
    cudaFuncSetAttribute(cgemm_kernel<false, false, true, false, true, false, true, false>,
                         cudaFuncAttributeMaxDynamicSharedMemorySize, SMEM_NN);
    cudaFuncSetAttribute(cgemm_kernel<false, false, true, true, true, false, true, false>,
                         cudaFuncAttributeMaxDynamicSharedMemorySize, SMEM_NN);
    cudaFuncSetAttribute(cgemm_kernel<false, false, true, true, false, false, true, false>,
                         cudaFuncAttributeMaxDynamicSharedMemorySize, SMEM_NN);

    static cudaStream_t s2 = nullptr;
    static cudaEvent_t evFork = nullptr, evJoin = nullptr;
    if (!s2) {
        cudaStreamCreateWithFlags(&s2, cudaStreamNonBlocking);
        cudaEventCreateWithFlags(&evFork, cudaEventDisableTiming);
        cudaEventCreateWithFlags(&evJoin, cudaEventDisableTiming);
    }

    const float scale = 0.03125f;                 // 1/sqrt(1024)
    const long long sQ = (long long)SEQ * MAN;
    const long long sS = (long long)SEQ * SEQ;
    const long long pMM = (long long)MAN * MAN;
    const long long pQ  = (long long)ROWS * MAN;
    const long long pS  = (long long)BATCH * SEQ * SEQ;
    const long long pW  = (long long)NLAYERS * pMM;

    // ---- main path start (launches 1-5) ----
    conv(x, cx, (long long)ROWS * HID);
    conv(Wp, cwp, (long long)MAN * HID);
    conv(aWr, cwr, pW);
    conv(aWi, cwi, pW);

    hgemm_b16_128(true, cx, (long long)ROWS * HID, cwp, (long long)MAN * HID,
                  cq0r, pQ, bp, ROWS, MAN, HID);

    bf16 *cqr = cq0r, *cqi = cq0i, *cqnr = cq1r, *cqni = cq1i;

    // ---- launch 6 (profiled): layer-0 a-cgemm ----
    {
        dim3 grid(MAN / 128, ROWS / 128, 1);
        cgemm_kernel<true, false, false, true, true, false, true, false><<<grid, 256, SMEM_NT>>>(
            cqr, cqi, pQ, cwr, cwi, pW,
            nullptr, nullptr, car, cai, pQ, abr, abi,
            ROWS, MAN, MAN, 0, 0, 0, 1.f);
    }

    // ---- fork: setup chain (cpost) on s2, overlapped with layers ----
    cudaEventRecord(evFork, 0);
    cudaStreamWaitEvent(s2, evFork, 0);
    conv(metric, cmet, pMM, s2);
    conv(Wpinv, cwpinv, (long long)HID * MAN, s2);
    {
        dim3 blk(16, 16), grd(MAN / 16, MAN / 16);
        build_mflow_kernel<<<grd, blk, 0, s2>>>(flowW, cm0, pMM);
    }
    hgemm_b16_64(false, cm0, pMM, cm0, pMM, cm1, pMM, MAN, MAN, MAN, s2);   // Mf^2
    hgemm_b16_64(false, cm1, pMM, cm1, pMM, cm2, pMM, MAN, MAN, MAN, s2);   // Mf^4
    hgemm_b16_64(false, cm2, pMM, cm2, pMM, cm0, pMM, MAN, MAN, MAN, s2);   // Mf^8
    hgemm_b16_64(false, cm0, pMM, cm1, pMM, cm2, pMM, MAN, MAN, MAN, s2);   // Mf^10
    hgemm_b16_64(false, cmet, pMM, cm2, pMM, cm1, pMM, MAN, MAN, MAN, s2);  // g*Mf^10
    hgemm_b16_64(true, cm1, pMM, cwpinv, (long long)HID * MAN, ccpost,
                 (long long)MAN * HID, MAN, HID, MAN, s2);                  // * Wpinv^T
    cudaEventRecord(evJoin, s2);

    for (int l = 0; l < NLAYERS; l++) {
        const bf16* Wr = cwr + (long long)l * pMM;
        const bf16* Wi = cwi + (long long)l * pMM;
        const float* br = abr + (long long)l * MAN;
        const float* bi = abi + (long long)l * MAN;

        // a = q (*) W^T + b   (layer 0 already launched above)
        if (l > 0) {
            dim3 grid(MAN / 128, ROWS / 128, 1);
            cgemm_kernel<true, false, true, true, true, false, true, false><<<grid, 256, SMEM_NT>>>(
                cqr, cqi, pQ, Wr, Wi, pW,
                nullptr, nullptr, car, cai, pQ, br, bi,
                ROWS, MAN, MAN, 0, 0, 0, 1.f);
        }

        // scores = scale * a (*) conj(a)^T  (Hermitian triangular + mirror)
        {
            dim3 grid(136, 1, BATCH);
            cgemm_kernel<true, true, true, true, true, true, false, true><<<grid, 256, SMEM_NT>>>(
                car, cai, pQ, car, cai, pQ,
                sr, si, nullptr, nullptr, pS, nullptr, nullptr,
                SEQ, SEQ, MAN, sQ, sQ, sS, scale);
        }

        csoftmax_kernel<<<BATCH * SEQ, 256>>>(sr, si, csr, csi, pS);

        // q' = attn (*) q
        {
            dim3 grid(MAN / 128, SEQ / 128, BATCH);
            if (l == 0)
                cgemm_kernel<false, false, true, false, true, false, true, false><<<grid, 256, SMEM_NN>>>(
                    csr, csi, pS, cqr, cqi, pQ,
                    nullptr, nullptr, cqnr, cqni, pQ, nullptr, nullptr,
                    SEQ, MAN, SEQ, sS, sQ, sQ, 1.f);
            else if (l < NLAYERS - 1)
                cgemm_kernel<false, false, true, true, true, false, true, false><<<grid, 256, SMEM_NN>>>(
                    csr, csi, pS, cqr, cqi, pQ,
                    nullptr, nullptr, cqnr, cqni, pQ, nullptr, nullptr,
                    SEQ, MAN, SEQ, sS, sQ, sQ, 1.f);
            else
                cgemm_kernel<false, false, true, true, false, false, true, false><<<grid, 256, SMEM_NN>>>(
                    csr, csi, pS, cqr, cqi, pQ,
                    nullptr, nullptr, cqnr, cqni, pQ, nullptr, nullptr,
                    SEQ, MAN, SEQ, sS, sQ, sQ, 1.f);
        }

        bf16* tr = cqr; cqr = cqnr; cqnr = tr;
        bf16* ti = cqi; cqi = cqni; cqni = ti;
    }

    // ---- join: wait for cpost chain, then final projection ----
    cudaStreamWaitEvent(0, evJoin, 0);
    hgemm_f32_nn(cqr, pQ, ccpost, (long long)MAN * HID, out, bpinv, ROWS, HID, MAN);
}